// round 6
// baseline (speedup 1.0000x reference)
#include <cuda_runtime.h>
#include <cstdint>

#define BATCH 4
#define TSEQ  2048
#define CDIM  2048
#define NHEAD 16
#define HDIM  128
#define MROWS (BATCH*TSEQ)   // 8192

// Scratch (device globals: no allocation allowed)
__device__ float g_q[(size_t)MROWS*CDIM];
__device__ float g_k[(size_t)MROWS*CDIM];
__device__ float g_v[(size_t)MROWS*CDIM];
__device__ float g_y[(size_t)MROWS*CDIM];

// ---------------------------------------------------------------------------
// SGEMM NT: C[m,n] = sum_k A[m,k] * W[n,k].  M = gridDim.y*128, N = K = 2048.
// 128x128x16 tiles, double-buffered smem, 256 threads, 8x8 (4+4 split) micro.
// Smem layout k-major with XOR swizzle: As[k*128 + (m ^ ((k&7)<<2))]
// ---------------------------------------------------------------------------
__global__ __launch_bounds__(256, 2)
void sgemm_nt(const float* __restrict__ A, const float* __restrict__ W,
              float* __restrict__ Cout)
{
    __shared__ float As[2][16*128];
    __shared__ float Bs[2][16*128];

    const int tid = threadIdx.x;
    const int tx  = tid & 15, ty = tid >> 4;
    const int tx4 = tx * 4,  ty4 = ty * 4;
    const int bm  = blockIdx.y * 128;
    const int bn  = blockIdx.x * 128;

    const int lm  = tid >> 2;          // 0..63
    const int lk4 = (tid & 3) * 4;     // 0,4,8,12

    const float* Aptr = A + (size_t)(bm + lm) * CDIM + lk4;
    const float* Wptr = W + (size_t)(bn + lm) * CDIM + lk4;

    float acc[8][8];
    #pragma unroll
    for (int i = 0; i < 8; i++)
        #pragma unroll
        for (int j = 0; j < 8; j++) acc[i][j] = 0.f;

    // initial tile load (kt = 0)
    {
        float4 a0 = *(const float4*)(Aptr);
        float4 a1 = *(const float4*)(Aptr + (size_t)64 * CDIM);
        float4 b0 = *(const float4*)(Wptr);
        float4 b1 = *(const float4*)(Wptr + (size_t)64 * CDIM);
        #pragma unroll
        for (int j = 0; j < 4; j++) {
            int k  = lk4 + j;
            int sw = (k & 7) << 2;
            float av0 = (j==0)?a0.x:(j==1)?a0.y:(j==2)?a0.z:a0.w;
            float av1 = (j==0)?a1.x:(j==1)?a1.y:(j==2)?a1.z:a1.w;
            float bv0 = (j==0)?b0.x:(j==1)?b0.y:(j==2)?b0.z:b0.w;
            float bv1 = (j==0)?b1.x:(j==1)?b1.y:(j==2)?b1.z:b1.w;
            As[0][k*128 + (lm        ^ sw)] = av0;
            As[0][k*128 + ((lm + 64) ^ sw)] = av1;
            Bs[0][k*128 + (lm        ^ sw)] = bv0;
            Bs[0][k*128 + ((lm + 64) ^ sw)] = bv1;
        }
    }
    __syncthreads();

    int buf = 0;
    const int KT = CDIM / 16;
    for (int kt = 0; kt < KT; ++kt) {
        float4 a0, a1, b0, b1;
        bool pf = (kt + 1 < KT);
        if (pf) {
            const float* Ap = Aptr + (kt + 1) * 16;
            const float* Wp = Wptr + (kt + 1) * 16;
            a0 = *(const float4*)(Ap);
            a1 = *(const float4*)(Ap + (size_t)64 * CDIM);
            b0 = *(const float4*)(Wp);
            b1 = *(const float4*)(Wp + (size_t)64 * CDIM);
        }
        const float* ab = As[buf];
        const float* bb = Bs[buf];
        #pragma unroll
        for (int k = 0; k < 16; k++) {
            int sw = (k & 7) << 2;
            const float* ar = ab + k * 128;
            const float* br = bb + k * 128;
            float4 fa0 = *(const float4*)(ar + (ty4 ^ sw));
            float4 fa1 = *(const float4*)(ar + 64 + (ty4 ^ sw));
            float4 fb0 = *(const float4*)(br + (tx4 ^ sw));
            float4 fb1 = *(const float4*)(br + 64 + (tx4 ^ sw));
            float av[8] = {fa0.x,fa0.y,fa0.z,fa0.w, fa1.x,fa1.y,fa1.z,fa1.w};
            float bv[8] = {fb0.x,fb0.y,fb0.z,fb0.w, fb1.x,fb1.y,fb1.z,fb1.w};
            #pragma unroll
            for (int i = 0; i < 8; i++)
                #pragma unroll
                for (int j = 0; j < 8; j++)
                    acc[i][j] += av[i] * bv[j];
        }
        if (pf) {
            int nb = buf ^ 1;
            #pragma unroll
            for (int j = 0; j < 4; j++) {
                int k  = lk4 + j;
                int sw = (k & 7) << 2;
                float av0 = (j==0)?a0.x:(j==1)?a0.y:(j==2)?a0.z:a0.w;
                float av1 = (j==0)?a1.x:(j==1)?a1.y:(j==2)?a1.z:a1.w;
                float bv0 = (j==0)?b0.x:(j==1)?b0.y:(j==2)?b0.z:b0.w;
                float bv1 = (j==0)?b1.x:(j==1)?b1.y:(j==2)?b1.z:b1.w;
                As[nb][k*128 + (lm        ^ sw)] = av0;
                As[nb][k*128 + ((lm + 64) ^ sw)] = av1;
                Bs[nb][k*128 + (lm        ^ sw)] = bv0;
                Bs[nb][k*128 + ((lm + 64) ^ sw)] = bv1;
            }
        }
        buf ^= 1;
        __syncthreads();
    }

    #pragma unroll
    for (int i = 0; i < 8; i++) {
        int m = bm + ((i < 4) ? (ty4 + i) : (64 + ty4 + i - 4));
        float* cp = Cout + (size_t)m * CDIM + bn;
        *(float4*)(cp + tx4)      = make_float4(acc[i][0], acc[i][1], acc[i][2], acc[i][3]);
        *(float4*)(cp + 64 + tx4) = make_float4(acc[i][4], acc[i][5], acc[i][6], acc[i][7]);
    }
}

// ---------------------------------------------------------------------------
// RoPE, in place on g_q and g_k.  grid (MROWS, NHEAD), block 64.
// out1 = x1*c + x2*s ; out2 = x1*c - x2*s
// ---------------------------------------------------------------------------
__global__ void rope_kernel(const float* __restrict__ cosp,
                            const float* __restrict__ sinp)
{
    int row = blockIdx.x;            // b*T + t
    int h   = blockIdx.y;
    int i   = threadIdx.x;           // 0..63
    int t   = row & (TSEQ - 1);
    float c = cosp[t * 64 + i];
    float s = sinp[t * 64 + i];
    float* qp = g_q + (size_t)row * CDIM + h * HDIM;
    float* kp = g_k + (size_t)row * CDIM + h * HDIM;
    float q1 = qp[i], q2 = qp[i + 64];
    qp[i]      = q1 * c + q2 * s;
    qp[i + 64] = q1 * c - q2 * s;
    float k1 = kp[i], k2 = kp[i + 64];
    kp[i]      = k1 * c + k2 * s;
    kp[i + 64] = k1 * c - k2 * s;
}

// ---------------------------------------------------------------------------
// Flash attention fp32. One block = (b, h, q-tile of 128). 256 threads.
// Smem: QsT (d-major, swizzled), KV (K d-major / V n-major, shared buffer),
// St (P^T, n-major, swizzled), plus per-row stats.
// ---------------------------------------------------------------------------
__global__ __launch_bounds__(256, 1)
void flash_kernel()
{
    extern __shared__ float sm[];
    float* QsT = sm;                    // 128*128
    float* KV  = sm + 128 * 128;        // 128*128 (K then V)
    float* St  = sm + 2 * 128 * 128;    // 128*128
    float* m_s = sm + 3 * 128 * 128;    // 128
    float* l_s = m_s + 128;             // 128
    float* c_s = l_s + 128;             // 128

    const int tid = threadIdx.x;
    const int tx  = tid & 15, ty = tid >> 4;
    const int tx4 = tx * 4,  ty4 = ty * 4;
    const int b   = blockIdx.z, h = blockIdx.y;
    const int t0  = blockIdx.x * 128;
    const float scale = 0.08838834764831845f;   // 1/sqrt(128)

    // Load Q tile transposed into QsT[d][m] with swizzle
    const float* qg = g_q + ((size_t)b * TSEQ + t0) * CDIM + h * HDIM;
    #pragma unroll
    for (int it = 0; it < 16; ++it) {
        int idx = tid + it * 256;
        int mm  = idx >> 5, d4 = idx & 31;
        float4 v = *(const float4*)(qg + (size_t)mm * CDIM + d4 * 4);
        int sw  = (d4 & 7) << 2;
        int mms = mm ^ sw;
        QsT[(d4 * 4 + 0) * 128 + mms] = v.x;
        QsT[(d4 * 4 + 1) * 128 + mms] = v.y;
        QsT[(d4 * 4 + 2) * 128 + mms] = v.z;
        QsT[(d4 * 4 + 3) * 128 + mms] = v.w;
    }
    if (tid < 128) { m_s[tid] = -1e30f; l_s[tid] = 0.f; }

    float o[8][8];
    #pragma unroll
    for (int i = 0; i < 8; i++)
        #pragma unroll
        for (int j = 0; j < 8; j++) o[i][j] = 0.f;

    __syncthreads();

    for (int kt = 0; kt < TSEQ / 128; ++kt) {
        // K tile transposed into KV[d][n]
        const float* kg = g_k + ((size_t)b * TSEQ + kt * 128) * CDIM + h * HDIM;
        #pragma unroll
        for (int it = 0; it < 16; ++it) {
            int idx = tid + it * 256;
            int nn  = idx >> 5, d4 = idx & 31;
            float4 v = *(const float4*)(kg + (size_t)nn * CDIM + d4 * 4);
            int sw  = (d4 & 7) << 2;
            int nns = nn ^ sw;
            KV[(d4 * 4 + 0) * 128 + nns] = v.x;
            KV[(d4 * 4 + 1) * 128 + nns] = v.y;
            KV[(d4 * 4 + 2) * 128 + nns] = v.z;
            KV[(d4 * 4 + 3) * 128 + nns] = v.w;
        }
        __syncthreads();

        // S = Q K^T
        float s[8][8];
        #pragma unroll
        for (int i = 0; i < 8; i++)
            #pragma unroll
            for (int j = 0; j < 8; j++) s[i][j] = 0.f;

        #pragma unroll 8
        for (int d = 0; d < 128; ++d) {
            int sw = ((d >> 2) & 7) << 2;
            const float* qr = QsT + d * 128;
            const float* kr = KV  + d * 128;
            float4 a0 = *(const float4*)(qr + (ty4 ^ sw));
            float4 a1 = *(const float4*)(qr + 64 + (ty4 ^ sw));
            float4 b0 = *(const float4*)(kr + (tx4 ^ sw));
            float4 b1 = *(const float4*)(kr + 64 + (tx4 ^ sw));
            float av[8] = {a0.x,a0.y,a0.z,a0.w, a1.x,a1.y,a1.z,a1.w};
            float bv[8] = {b0.x,b0.y,b0.z,b0.w, b1.x,b1.y,b1.z,b1.w};
            #pragma unroll
            for (int i = 0; i < 8; i++)
                #pragma unroll
                for (int j = 0; j < 8; j++)
                    s[i][j] += av[i] * bv[j];
        }

        // store scaled S transposed: St[n][m]
        #pragma unroll
        for (int j = 0; j < 8; j++) {
            int n  = (j < 4) ? (tx4 + j) : (64 + tx4 + j - 4);
            int sw = ((n >> 2) & 7) << 2;
            float* sr = St + n * 128;
            #pragma unroll
            for (int i = 0; i < 8; i++) {
                int m = (i < 4) ? (ty4 + i) : (64 + ty4 + i - 4);
                sr[m ^ sw] = s[i][j] * scale;
            }
        }
        __syncthreads();

        // softmax (warps 0-3) || V tile load (warps 4-7)
        if (tid < 128) {
            int r = tid;
            float mold = m_s[r];
            float mx = mold;
            #pragma unroll 8
            for (int n = 0; n < 128; n++) {
                int sw = ((n >> 2) & 7) << 2;
                mx = fmaxf(mx, St[n * 128 + (r ^ sw)]);
            }
            float corr = __expf(mold - mx);
            float sum = 0.f;
            #pragma unroll 8
            for (int n = 0; n < 128; n++) {
                int sw = ((n >> 2) & 7) << 2;
                float* p = St + n * 128 + (r ^ sw);
                float e = __expf(*p - mx);
                *p = e;
                sum += e;
            }
            m_s[r] = mx;
            l_s[r] = l_s[r] * corr + sum;
            c_s[r] = corr;
        } else {
            const float* vg = g_v + ((size_t)b * TSEQ + kt * 128) * CDIM + h * HDIM;
            #pragma unroll
            for (int it = 0; it < 32; ++it) {
                int idx = (tid - 128) + it * 128;
                int nn  = idx >> 5, c4 = idx & 31;
                float4 v = *(const float4*)(vg + (size_t)nn * CDIM + c4 * 4);
                int sw  = (nn >> 2) & 7;
                *(float4*)(KV + nn * 128 + ((c4 ^ sw) << 2)) = v;
            }
        }
        __syncthreads();

        // rescale O, then O += P V
        float cr[8];
        #pragma unroll
        for (int i = 0; i < 8; i++) {
            int m = (i < 4) ? (ty4 + i) : (64 + ty4 + i - 4);
            cr[i] = c_s[m];
        }
        #pragma unroll
        for (int i = 0; i < 8; i++)
            #pragma unroll
            for (int j = 0; j < 8; j++) o[i][j] *= cr[i];

        #pragma unroll 8
        for (int n = 0; n < 128; ++n) {
            int sw = ((n >> 2) & 7) << 2;
            const float* pr = St + n * 128;
            const float* vr = KV + n * 128;
            float4 p0 = *(const float4*)(pr + (ty4 ^ sw));
            float4 p1 = *(const float4*)(pr + 64 + (ty4 ^ sw));
            float4 v0 = *(const float4*)(vr + (tx4 ^ sw));
            float4 v1 = *(const float4*)(vr + 64 + (tx4 ^ sw));
            float pv[8] = {p0.x,p0.y,p0.z,p0.w, p1.x,p1.y,p1.z,p1.w};
            float vv[8] = {v0.x,v0.y,v0.z,v0.w, v1.x,v1.y,v1.z,v1.w};
            #pragma unroll
            for (int i = 0; i < 8; i++)
                #pragma unroll
                for (int j = 0; j < 8; j++)
                    o[i][j] += pv[i] * vv[j];
        }
        __syncthreads();   // protect KV/St before next iteration overwrites
    }

    // epilogue: O /= l, write y[b, t, h, d]
    float* yg = g_y + ((size_t)b * TSEQ + t0) * CDIM + h * HDIM;
    #pragma unroll
    for (int i = 0; i < 8; i++) {
        int m = (i < 4) ? (ty4 + i) : (64 + ty4 + i - 4);
        float inv = 1.0f / l_s[m];
        float4 r0 = make_float4(o[i][0]*inv, o[i][1]*inv, o[i][2]*inv, o[i][3]*inv);
        float4 r1 = make_float4(o[i][4]*inv, o[i][5]*inv, o[i][6]*inv, o[i][7]*inv);
        *(float4*)(yg + (size_t)m * CDIM + tx4)      = r0;
        *(float4*)(yg + (size_t)m * CDIM + 64 + tx4) = r1;
    }
}

// ---------------------------------------------------------------------------
extern "C" void kernel_launch(void* const* d_in, const int* in_sizes, int n_in,
                              void* d_out, int out_size)
{
    (void)in_sizes; (void)n_in; (void)out_size;
    const float* x    = (const float*)d_in[0];
    const float* cosp = (const float*)d_in[1];
    const float* sinp = (const float*)d_in[2];
    const float* wq   = (const float*)d_in[3];
    const float* wk   = (const float*)d_in[4];
    const float* wv   = (const float*)d_in[5];
    const float* wo   = (const float*)d_in[6];
    float* out = (float*)d_out;

    float *q, *k, *v, *y;
    cudaGetSymbolAddress((void**)&q, g_q);
    cudaGetSymbolAddress((void**)&k, g_k);
    cudaGetSymbolAddress((void**)&v, g_v);
    cudaGetSymbolAddress((void**)&y, g_y);

    dim3 gg(CDIM / 128, MROWS / 128);   // (16, 64)

    sgemm_nt<<<gg, 256>>>(x, wq, q);
    sgemm_nt<<<gg, 256>>>(x, wk, k);
    sgemm_nt<<<gg, 256>>>(x, wv, v);

    rope_kernel<<<dim3(MROWS, NHEAD), 64>>>(cosp, sinp);

    size_t smem = (3 * 128 * 128 + 3 * 128) * sizeof(float);  // 198,144 B
    cudaFuncSetAttribute(flash_kernel,
                         cudaFuncAttributeMaxDynamicSharedMemorySize, (int)smem);
    flash_kernel<<<dim3(TSEQ / 128, NHEAD, BATCH), 256, smem>>>();

    sgemm_nt<<<gg, 256>>>(y, wo, out);
}

// round 9
// speedup vs baseline: 1.1192x; 1.1192x over previous
#include <cuda_runtime.h>
#include <cstdint>

#define BATCH 4
#define TSEQ  2048
#define CDIM  2048
#define NHEAD 16
#define HDIM  128
#define MROWS (BATCH*TSEQ)   // 8192

// Scratch (device globals: no allocation allowed)
__device__ float g_q[(size_t)MROWS*CDIM];
__device__ float g_k[(size_t)MROWS*CDIM];
__device__ float g_v[(size_t)MROWS*CDIM];
__device__ float g_y[(size_t)MROWS*CDIM];

// ---------------------------------------------------------------------------
// Packed f32x2 helpers (Blackwell FFMA2 path — ptxas never auto-emits these)
// ---------------------------------------------------------------------------
__device__ __forceinline__ unsigned long long pack2(float x, float y) {
    unsigned long long r;
    asm("mov.b64 %0, {%1, %2};" : "=l"(r) : "f"(x), "f"(y));
    return r;
}
__device__ __forceinline__ unsigned long long dup2(float x) {
    unsigned long long r;
    asm("mov.b64 %0, {%1, %1};" : "=l"(r) : "f"(x));
    return r;
}
__device__ __forceinline__ void unpack2(unsigned long long v, float& x, float& y) {
    asm("mov.b64 {%0, %1}, %2;" : "=f"(x), "=f"(y) : "l"(v));
}
__device__ __forceinline__ unsigned long long fma2(unsigned long long a,
                                                   unsigned long long b,
                                                   unsigned long long c) {
    unsigned long long d;
    asm("fma.rn.f32x2 %0, %1, %2, %3;" : "=l"(d) : "l"(a), "l"(b), "l"(c));
    return d;
}
__device__ __forceinline__ unsigned long long mul2(unsigned long long a,
                                                   unsigned long long b) {
    unsigned long long d;
    asm("mul.rn.f32x2 %0, %1, %2;" : "=l"(d) : "l"(a), "l"(b));
    return d;
}

// ---------------------------------------------------------------------------
// SGEMM NT: C[m,n] = sum_k A[m,k] * W[n,k].  M = gridDim.y*128, N = K = 2048.
// 128x128x16 tiles, double-buffered smem, 256 threads, 8x8 (4+4 split) micro,
// packed-f32x2 accumulators along n.
// Smem layout k-major with XOR swizzle: As[k*128 + (m ^ ((k&7)<<2))]
// ---------------------------------------------------------------------------
__global__ __launch_bounds__(256, 2)
void sgemm_nt(const float* __restrict__ A, const float* __restrict__ W,
              float* __restrict__ Cout)
{
    __shared__ float As[2][16*128];
    __shared__ float Bs[2][16*128];

    const int tid = threadIdx.x;
    const int tx  = tid & 15, ty = tid >> 4;
    const int tx4 = tx * 4,  ty4 = ty * 4;
    const int bm  = blockIdx.y * 128;
    const int bn  = blockIdx.x * 128;

    const int lm  = tid >> 2;          // 0..63
    const int lk4 = (tid & 3) * 4;     // 0,4,8,12

    const float* Aptr = A + (size_t)(bm + lm) * CDIM + lk4;
    const float* Wptr = W + (size_t)(bn + lm) * CDIM + lk4;

    unsigned long long acc2[8][4];
    #pragma unroll
    for (int i = 0; i < 8; i++)
        #pragma unroll
        for (int j = 0; j < 4; j++) acc2[i][j] = 0ull;

    // initial tile load (kt = 0)
    {
        float4 a0 = *(const float4*)(Aptr);
        float4 a1 = *(const float4*)(Aptr + (size_t)64 * CDIM);
        float4 b0 = *(const float4*)(Wptr);
        float4 b1 = *(const float4*)(Wptr + (size_t)64 * CDIM);
        #pragma unroll
        for (int j = 0; j < 4; j++) {
            int k  = lk4 + j;
            int sw = (k & 7) << 2;
            float av0 = (j==0)?a0.x:(j==1)?a0.y:(j==2)?a0.z:a0.w;
            float av1 = (j==0)?a1.x:(j==1)?a1.y:(j==2)?a1.z:a1.w;
            float bv0 = (j==0)?b0.x:(j==1)?b0.y:(j==2)?b0.z:b0.w;
            float bv1 = (j==0)?b1.x:(j==1)?b1.y:(j==2)?b1.z:b1.w;
            As[0][k*128 + (lm        ^ sw)] = av0;
            As[0][k*128 + ((lm + 64) ^ sw)] = av1;
            Bs[0][k*128 + (lm        ^ sw)] = bv0;
            Bs[0][k*128 + ((lm + 64) ^ sw)] = bv1;
        }
    }
    __syncthreads();

    int buf = 0;
    const int KT = CDIM / 16;
    for (int kt = 0; kt < KT; ++kt) {
        float4 a0, a1, b0, b1;
        bool pf = (kt + 1 < KT);
        if (pf) {
            const float* Ap = Aptr + (kt + 1) * 16;
            const float* Wp = Wptr + (kt + 1) * 16;
            a0 = *(const float4*)(Ap);
            a1 = *(const float4*)(Ap + (size_t)64 * CDIM);
            b0 = *(const float4*)(Wp);
            b1 = *(const float4*)(Wp + (size_t)64 * CDIM);
        }
        const float* ab = As[buf];
        const float* bb = Bs[buf];
        #pragma unroll
        for (int k = 0; k < 16; k++) {
            int sw = (k & 7) << 2;
            const float* ar = ab + k * 128;
            const float* br = bb + k * 128;
            float4 fa0 = *(const float4*)(ar + (ty4 ^ sw));
            float4 fa1 = *(const float4*)(ar + 64 + (ty4 ^ sw));
            ulonglong2 ub0 = *(const ulonglong2*)(br + (tx4 ^ sw));
            ulonglong2 ub1 = *(const ulonglong2*)(br + 64 + (tx4 ^ sw));
            unsigned long long bv2[4] = {ub0.x, ub0.y, ub1.x, ub1.y};
            unsigned long long av2[8] = {dup2(fa0.x), dup2(fa0.y), dup2(fa0.z), dup2(fa0.w),
                                         dup2(fa1.x), dup2(fa1.y), dup2(fa1.z), dup2(fa1.w)};
            #pragma unroll
            for (int i = 0; i < 8; i++)
                #pragma unroll
                for (int j = 0; j < 4; j++)
                    acc2[i][j] = fma2(av2[i], bv2[j], acc2[i][j]);
        }
        if (pf) {
            int nb = buf ^ 1;
            #pragma unroll
            for (int j = 0; j < 4; j++) {
                int k  = lk4 + j;
                int sw = (k & 7) << 2;
                float av0 = (j==0)?a0.x:(j==1)?a0.y:(j==2)?a0.z:a0.w;
                float av1 = (j==0)?a1.x:(j==1)?a1.y:(j==2)?a1.z:a1.w;
                float bv0 = (j==0)?b0.x:(j==1)?b0.y:(j==2)?b0.z:b0.w;
                float bv1 = (j==0)?b1.x:(j==1)?b1.y:(j==2)?b1.z:b1.w;
                As[nb][k*128 + (lm        ^ sw)] = av0;
                As[nb][k*128 + ((lm + 64) ^ sw)] = av1;
                Bs[nb][k*128 + (lm        ^ sw)] = bv0;
                Bs[nb][k*128 + ((lm + 64) ^ sw)] = bv1;
            }
        }
        buf ^= 1;
        __syncthreads();
    }

    #pragma unroll
    for (int i = 0; i < 8; i++) {
        int m = bm + ((i < 4) ? (ty4 + i) : (64 + ty4 + i - 4));
        float* cp = Cout + (size_t)m * CDIM + bn;
        float r[8];
        unpack2(acc2[i][0], r[0], r[1]);
        unpack2(acc2[i][1], r[2], r[3]);
        unpack2(acc2[i][2], r[4], r[5]);
        unpack2(acc2[i][3], r[6], r[7]);
        *(float4*)(cp + tx4)      = make_float4(r[0], r[1], r[2], r[3]);
        *(float4*)(cp + 64 + tx4) = make_float4(r[4], r[5], r[6], r[7]);
    }
}

// ---------------------------------------------------------------------------
// RoPE, in place on g_q and g_k.  grid (MROWS, NHEAD), block 64.
// ---------------------------------------------------------------------------
__global__ void rope_kernel(const float* __restrict__ cosp,
                            const float* __restrict__ sinp)
{
    int row = blockIdx.x;            // b*T + t
    int h   = blockIdx.y;
    int i   = threadIdx.x;           // 0..63
    int t   = row & (TSEQ - 1);
    float c = cosp[t * 64 + i];
    float s = sinp[t * 64 + i];
    float* qp = g_q + (size_t)row * CDIM + h * HDIM;
    float* kp = g_k + (size_t)row * CDIM + h * HDIM;
    float q1 = qp[i], q2 = qp[i + 64];
    qp[i]      = q1 * c + q2 * s;
    qp[i + 64] = q1 * c - q2 * s;
    float k1 = kp[i], k2 = kp[i + 64];
    kp[i]      = k1 * c + k2 * s;
    kp[i + 64] = k1 * c - k2 * s;
}

// ---------------------------------------------------------------------------
// Flash attention fp32 with packed-f32x2 MMA loops. One block = (b, h,
// q-tile of 128). 256 threads.
// ---------------------------------------------------------------------------
__global__ __launch_bounds__(256, 1)
void flash_kernel()
{
    extern __shared__ float sm[];
    float* QsT = sm;                    // 128*128
    float* KV  = sm + 128 * 128;        // 128*128 (K then V)
    float* St  = sm + 2 * 128 * 128;    // 128*128
    float* m_s = sm + 3 * 128 * 128;    // 128
    float* l_s = m_s + 128;             // 128
    float* c_s = l_s + 128;             // 128

    const int tid = threadIdx.x;
    const int tx  = tid & 15, ty = tid >> 4;
    const int tx4 = tx * 4,  ty4 = ty * 4;
    const int b   = blockIdx.z, h = blockIdx.y;
    const int t0  = blockIdx.x * 128;
    const float scale = 0.08838834764831845f;   // 1/sqrt(128)

    // Load Q tile transposed into QsT[d][m] with swizzle
    const float* qg = g_q + ((size_t)b * TSEQ + t0) * CDIM + h * HDIM;
    #pragma unroll
    for (int it = 0; it < 16; ++it) {
        int idx = tid + it * 256;
        int mm  = idx >> 5, d4 = idx & 31;
        float4 v = *(const float4*)(qg + (size_t)mm * CDIM + d4 * 4);
        int sw  = (d4 & 7) << 2;
        int mms = mm ^ sw;
        QsT[(d4 * 4 + 0) * 128 + mms] = v.x;
        QsT[(d4 * 4 + 1) * 128 + mms] = v.y;
        QsT[(d4 * 4 + 2) * 128 + mms] = v.z;
        QsT[(d4 * 4 + 3) * 128 + mms] = v.w;
    }
    if (tid < 128) { m_s[tid] = -1e30f; l_s[tid] = 0.f; }

    unsigned long long o2[8][4];
    #pragma unroll
    for (int i = 0; i < 8; i++)
        #pragma unroll
        for (int j = 0; j < 4; j++) o2[i][j] = 0ull;

    __syncthreads();

    for (int kt = 0; kt < TSEQ / 128; ++kt) {
        // K tile transposed into KV[d][n]
        const float* kg = g_k + ((size_t)b * TSEQ + kt * 128) * CDIM + h * HDIM;
        #pragma unroll
        for (int it = 0; it < 16; ++it) {
            int idx = tid + it * 256;
            int nn  = idx >> 5, d4 = idx & 31;
            float4 v = *(const float4*)(kg + (size_t)nn * CDIM + d4 * 4);
            int sw  = (d4 & 7) << 2;
            int nns = nn ^ sw;
            KV[(d4 * 4 + 0) * 128 + nns] = v.x;
            KV[(d4 * 4 + 1) * 128 + nns] = v.y;
            KV[(d4 * 4 + 2) * 128 + nns] = v.z;
            KV[(d4 * 4 + 3) * 128 + nns] = v.w;
        }
        __syncthreads();

        // S = Q K^T  (packed along n)
        unsigned long long s2[8][4];
        #pragma unroll
        for (int i = 0; i < 8; i++)
            #pragma unroll
            for (int j = 0; j < 4; j++) s2[i][j] = 0ull;

        #pragma unroll 8
        for (int d = 0; d < 128; ++d) {
            int sw = ((d >> 2) & 7) << 2;
            const float* qr = QsT + d * 128;
            const float* kr = KV  + d * 128;
            float4 a0 = *(const float4*)(qr + (ty4 ^ sw));
            float4 a1 = *(const float4*)(qr + 64 + (ty4 ^ sw));
            ulonglong2 ub0 = *(const ulonglong2*)(kr + (tx4 ^ sw));
            ulonglong2 ub1 = *(const ulonglong2*)(kr + 64 + (tx4 ^ sw));
            unsigned long long bv2[4] = {ub0.x, ub0.y, ub1.x, ub1.y};
            unsigned long long av2[8] = {dup2(a0.x), dup2(a0.y), dup2(a0.z), dup2(a0.w),
                                         dup2(a1.x), dup2(a1.y), dup2(a1.z), dup2(a1.w)};
            #pragma unroll
            for (int i = 0; i < 8; i++)
                #pragma unroll
                for (int j = 0; j < 4; j++)
                    s2[i][j] = fma2(av2[i], bv2[j], s2[i][j]);
        }

        // store scaled S transposed: St[n][m]
        #pragma unroll
        for (int i = 0; i < 8; i++) {
            int m = (i < 4) ? (ty4 + i) : (64 + ty4 + i - 4);
            float sv[8];
            unpack2(s2[i][0], sv[0], sv[1]);
            unpack2(s2[i][1], sv[2], sv[3]);
            unpack2(s2[i][2], sv[4], sv[5]);
            unpack2(s2[i][3], sv[6], sv[7]);
            #pragma unroll
            for (int j = 0; j < 8; j++) {
                int n  = (j < 4) ? (tx4 + j) : (64 + tx4 + j - 4);
                int sw = ((n >> 2) & 7) << 2;
                St[n * 128 + (m ^ sw)] = sv[j] * scale;
            }
        }
        __syncthreads();

        // softmax (warps 0-3) || V tile load (warps 4-7)
        if (tid < 128) {
            int r = tid;
            float mold = m_s[r];
            float mx = mold;
            #pragma unroll 8
            for (int n = 0; n < 128; n++) {
                int sw = ((n >> 2) & 7) << 2;
                mx = fmaxf(mx, St[n * 128 + (r ^ sw)]);
            }
            float corr = __expf(mold - mx);
            float sum = 0.f;
            #pragma unroll 8
            for (int n = 0; n < 128; n++) {
                int sw = ((n >> 2) & 7) << 2;
                float* p = St + n * 128 + (r ^ sw);
                float e = __expf(*p - mx);
                *p = e;
                sum += e;
            }
            m_s[r] = mx;
            l_s[r] = l_s[r] * corr + sum;
            c_s[r] = corr;
        } else {
            const float* vg = g_v + ((size_t)b * TSEQ + kt * 128) * CDIM + h * HDIM;
            #pragma unroll
            for (int it = 0; it < 32; ++it) {
                int idx = (tid - 128) + it * 128;
                int nn  = idx >> 5, c4 = idx & 31;
                float4 v = *(const float4*)(vg + (size_t)nn * CDIM + c4 * 4);
                int sw  = (nn >> 2) & 7;
                *(float4*)(KV + nn * 128 + ((c4 ^ sw) << 2)) = v;
            }
        }
        __syncthreads();

        // rescale O (packed), then O += P V (packed)
        #pragma unroll
        for (int i = 0; i < 8; i++) {
            int m = (i < 4) ? (ty4 + i) : (64 + ty4 + i - 4);
            unsigned long long crp = dup2(c_s[m]);
            #pragma unroll
            for (int j = 0; j < 4; j++) o2[i][j] = mul2(o2[i][j], crp);
        }

        #pragma unroll 8
        for (int n = 0; n < 128; ++n) {
            int sw = ((n >> 2) & 7) << 2;
            const float* pr = St + n * 128;
            const float* vr = KV + n * 128;
            float4 p0 = *(const float4*)(pr + (ty4 ^ sw));
            float4 p1 = *(const float4*)(pr + 64 + (ty4 ^ sw));
            ulonglong2 uv0 = *(const ulonglong2*)(vr + (tx4 ^ sw));
            ulonglong2 uv1 = *(const ulonglong2*)(vr + 64 + (tx4 ^ sw));
            unsigned long long vv2[4] = {uv0.x, uv0.y, uv1.x, uv1.y};
            unsigned long long pv2[8] = {dup2(p0.x), dup2(p0.y), dup2(p0.z), dup2(p0.w),
                                         dup2(p1.x), dup2(p1.y), dup2(p1.z), dup2(p1.w)};
            #pragma unroll
            for (int i = 0; i < 8; i++)
                #pragma unroll
                for (int j = 0; j < 4; j++)
                    o2[i][j] = fma2(pv2[i], vv2[j], o2[i][j]);
        }
        __syncthreads();   // protect KV/St before next iteration overwrites
    }

    // epilogue: O /= l, write y[b, t, h, d]
    float* yg = g_y + ((size_t)b * TSEQ + t0) * CDIM + h * HDIM;
    #pragma unroll
    for (int i = 0; i < 8; i++) {
        int m = (i < 4) ? (ty4 + i) : (64 + ty4 + i - 4);
        float inv = 1.0f / l_s[m];
        float r[8];
        unpack2(o2[i][0], r[0], r[1]);
        unpack2(o2[i][1], r[2], r[3]);
        unpack2(o2[i][2], r[4], r[5]);
        unpack2(o2[i][3], r[6], r[7]);
        float4 r0 = make_float4(r[0]*inv, r[1]*inv, r[2]*inv, r[3]*inv);
        float4 r1 = make_float4(r[4]*inv, r[5]*inv, r[6]*inv, r[7]*inv);
        *(float4*)(yg + (size_t)m * CDIM + tx4)      = r0;
        *(float4*)(yg + (size_t)m * CDIM + 64 + tx4) = r1;
    }
}

// ---------------------------------------------------------------------------
extern "C" void kernel_launch(void* const* d_in, const int* in_sizes, int n_in,
                              void* d_out, int out_size)
{
    (void)in_sizes; (void)n_in; (void)out_size;
    const float* x    = (const float*)d_in[0];
    const float* cosp = (const float*)d_in[1];
    const float* sinp = (const float*)d_in[2];
    const float* wq   = (const float*)d_in[3];
    const float* wk   = (const float*)d_in[4];
    const float* wv   = (const float*)d_in[5];
    const float* wo   = (const float*)d_in[6];
    float* out = (float*)d_out;

    float *q, *k, *v, *y;
    cudaGetSymbolAddress((void**)&q, g_q);
    cudaGetSymbolAddress((void**)&k, g_k);
    cudaGetSymbolAddress((void**)&v, g_v);
    cudaGetSymbolAddress((void**)&y, g_y);

    dim3 gg(CDIM / 128, MROWS / 128);   // (16, 64)

    sgemm_nt<<<gg, 256>>>(x, wq, q);
    sgemm_nt<<<gg, 256>>>(x, wk, k);
    sgemm_nt<<<gg, 256>>>(x, wv, v);

    rope_kernel<<<dim3(MROWS, NHEAD), 64>>>(cosp, sinp);

    size_t smem = (3 * 128 * 128 + 3 * 128) * sizeof(float);  // 198,144 B
    cudaFuncSetAttribute(flash_kernel,
                         cudaFuncAttributeMaxDynamicSharedMemorySize, (int)smem);
    flash_kernel<<<dim3(TSEQ / 128, NHEAD, BATCH), 256, smem>>>();

    sgemm_nt<<<gg, 256>>>(y, wo, out);
}

// round 11
// speedup vs baseline: 1.4771x; 1.3198x over previous
#include <cuda_runtime.h>
#include <cuda_bf16.h>
#include <cstdint>

#define BATCH 4
#define TSEQ  2048
#define CDIM  2048
#define NHEAD 16
#define HDIM  128
#define MROWS (BATCH*TSEQ)   // 8192

// ---------------------------------------------------------------------------
// Device-global scratch (no allocations allowed)
// ---------------------------------------------------------------------------
__device__ float g_q[(size_t)MROWS*CDIM];
__device__ float g_k[(size_t)MROWS*CDIM];
__device__ float g_v[(size_t)MROWS*CDIM];
__device__ float g_y[(size_t)MROWS*CDIM];

__device__ __nv_bfloat16 g_xhi[(size_t)MROWS*CDIM];
__device__ __nv_bfloat16 g_xlo[(size_t)MROWS*CDIM];
__device__ __nv_bfloat16 g_yhi[(size_t)MROWS*CDIM];
__device__ __nv_bfloat16 g_ylo[(size_t)MROWS*CDIM];
__device__ __nv_bfloat16 g_whi[4][(size_t)CDIM*CDIM];
__device__ __nv_bfloat16 g_wlo[4][(size_t)CDIM*CDIM];

extern __shared__ unsigned char dynsmem[];

// ---------------------------------------------------------------------------
// Helpers
// ---------------------------------------------------------------------------
__device__ __forceinline__ uint32_t smem_u32(const void* p) {
    uint32_t a;
    asm("{ .reg .u64 t; cvta.to.shared.u64 t, %1; cvt.u32.u64 %0, t; }"
        : "=r"(a) : "l"(p));
    return a;
}

#define LDSM4(r, addr) \
    asm volatile("ldmatrix.sync.aligned.m8n8.x4.shared.b16 {%0,%1,%2,%3}, [%4];" \
        : "=r"((r)[0]), "=r"((r)[1]), "=r"((r)[2]), "=r"((r)[3]) : "r"(addr))

__device__ __forceinline__ void mma_bf16(float* c, const uint32_t* a,
                                         uint32_t b0, uint32_t b1) {
    asm volatile(
        "mma.sync.aligned.m16n8k16.row.col.f32.bf16.bf16.f32 "
        "{%0,%1,%2,%3}, {%4,%5,%6,%7}, {%8,%9}, {%0,%1,%2,%3};"
        : "+f"(c[0]), "+f"(c[1]), "+f"(c[2]), "+f"(c[3])
        : "r"(a[0]), "r"(a[1]), "r"(a[2]), "r"(a[3]), "r"(b0), "r"(b1));
}

// Packed f32x2 helpers (flash kernel)
__device__ __forceinline__ unsigned long long dup2(float x) {
    unsigned long long r;
    asm("mov.b64 %0, {%1, %1};" : "=l"(r) : "f"(x));
    return r;
}
__device__ __forceinline__ void unpack2(unsigned long long v, float& x, float& y) {
    asm("mov.b64 {%0, %1}, %2;" : "=f"(x), "=f"(y) : "l"(v));
}
__device__ __forceinline__ unsigned long long fma2(unsigned long long a,
                                                   unsigned long long b,
                                                   unsigned long long c) {
    unsigned long long d;
    asm("fma.rn.f32x2 %0, %1, %2, %3;" : "=l"(d) : "l"(a), "l"(b), "l"(c));
    return d;
}
__device__ __forceinline__ unsigned long long mul2(unsigned long long a,
                                                   unsigned long long b) {
    unsigned long long d;
    asm("mul.rn.f32x2 %0, %1, %2;" : "=l"(d) : "l"(a), "l"(b));
    return d;
}

// ---------------------------------------------------------------------------
// fp32 -> bf16 hi/lo split (2-term), vectorized x4
// ---------------------------------------------------------------------------
__global__ void split_kernel(const float* __restrict__ src,
                             __nv_bfloat16* __restrict__ hi,
                             __nv_bfloat16* __restrict__ lo, int n4)
{
    int i = blockIdx.x * blockDim.x + threadIdx.x;
    if (i >= n4) return;
    float4 v = ((const float4*)src)[i];
    float vv[4] = {v.x, v.y, v.z, v.w};
    unsigned int hw[2], lw[2];
    #pragma unroll
    for (int p = 0; p < 2; p++) {
        float a = vv[2*p], b = vv[2*p+1];
        __nv_bfloat16 ha = __float2bfloat16(a);
        __nv_bfloat16 hb = __float2bfloat16(b);
        __nv_bfloat16 la = __float2bfloat16(a - __bfloat162float(ha));
        __nv_bfloat16 lb = __float2bfloat16(b - __bfloat162float(hb));
        hw[p] = (unsigned)__bfloat16_as_ushort(ha) |
                ((unsigned)__bfloat16_as_ushort(hb) << 16);
        lw[p] = (unsigned)__bfloat16_as_ushort(la) |
                ((unsigned)__bfloat16_as_ushort(lb) << 16);
    }
    ((uint2*)hi)[i] = make_uint2(hw[0], hw[1]);
    ((uint2*)lo)[i] = make_uint2(lw[0], lw[1]);
}

// ---------------------------------------------------------------------------
// mma.sync bf16 split GEMM: C[m,n] = sum_k A[m,k]*B[n,k] (fp32-accurate,
// 3-term bf16 split).  128x128x32 CTA tile, 8 warps (2M x 4N), double-buffered
// smem, 80B-padded rows (conflict-free ldmatrix).
// ---------------------------------------------------------------------------
#define OPB   10240          // 128 rows * 80 B
#define BUFB  (4*OPB)        // Ahi,Alo,Bhi,Blo
#define GSMEM (2*BUFB)       // 81,920 B

__global__ __launch_bounds__(256)
void gemm_mma(const __nv_bfloat16* __restrict__ Ahi, const __nv_bfloat16* __restrict__ Alo,
              const __nv_bfloat16* __restrict__ Bhi, const __nv_bfloat16* __restrict__ Blo,
              float* __restrict__ Cout)
{
    const int tid  = threadIdx.x;
    const int lane = tid & 31, wid = tid >> 5;
    const int wm   = wid & 1, wn = wid >> 1;       // 2 x 4 warp grid
    const int bm   = blockIdx.y * 128, bn = blockIdx.x * 128;

    // gmem load slice: thread -> (row, 32B half-row)
    const int lrow = tid >> 1;          // 0..127
    const int lu   = (tid & 1) * 2;     // unit 0 or 2 (16B units)
    const __nv_bfloat16* gsrc[4] = {
        Ahi + (size_t)(bm + lrow) * CDIM + lu * 8,
        Alo + (size_t)(bm + lrow) * CDIM + lu * 8,
        Bhi + (size_t)(bn + lrow) * CDIM + lu * 8,
        Blo + (size_t)(bn + lrow) * CDIM + lu * 8 };
    const uint32_t sdst_off = (uint32_t)(lrow * 80 + lu * 16);

    // ldmatrix per-thread offsets
    const int rowA = ((lane >> 3) & 1) * 8 + (lane & 7);
    const uint32_t aoff = (uint32_t)((wm * 64 + rowA) * 80 + (lane >> 4) * 16);
    const int rowB = ((lane >> 4) & 1) * 8 + (lane & 7);
    const uint32_t boff = (uint32_t)((wn * 32 + rowB) * 80 + ((lane >> 3) & 1) * 16);

    float acc[4][4][4];
    #pragma unroll
    for (int i = 0; i < 4; i++)
        #pragma unroll
        for (int n = 0; n < 4; n++)
            #pragma unroll
            for (int r = 0; r < 4; r++) acc[i][n][r] = 0.f;

    const uint32_t sb = smem_u32(dynsmem);

    // preload chunk 0 into buffer 0
    {
        #pragma unroll
        for (int op = 0; op < 4; op++) {
            int4 v0 = *(const int4*)(gsrc[op]);
            int4 v1 = *(const int4*)(gsrc[op] + 8);
            unsigned char* d = dynsmem + op * OPB + sdst_off;
            *(int4*)(d)      = v0;
            *(int4*)(d + 16) = v1;
        }
    }
    __syncthreads();

    const int NCHUNK = CDIM / 32;   // 64
    for (int c = 0; c < NCHUNK; ++c) {
        const int buf = c & 1;
        int4 v[4][2];
        const bool pf = (c + 1 < NCHUNK);
        if (pf) {
            #pragma unroll
            for (int op = 0; op < 4; op++) {
                const __nv_bfloat16* s = gsrc[op] + (c + 1) * 32;
                v[op][0] = *(const int4*)(s);
                v[op][1] = *(const int4*)(s + 8);
            }
        }

        const uint32_t base  = sb + buf * BUFB;
        const uint32_t sa_hi = base;
        const uint32_t sa_lo = base + OPB;
        const uint32_t sb_hi = base + 2 * OPB;
        const uint32_t sb_lo = base + 3 * OPB;

        #pragma unroll
        for (int ks = 0; ks < 2; ++ks) {
            uint32_t ah[4][4], al[4][4];
            #pragma unroll
            for (int i = 0; i < 4; i++) {
                LDSM4(ah[i], sa_hi + aoff + i * 1280 + ks * 32);
                LDSM4(al[i], sa_lo + aoff + i * 1280 + ks * 32);
            }
            #pragma unroll
            for (int p = 0; p < 2; p++) {
                uint32_t bh[4], bl[4];
                LDSM4(bh, sb_hi + boff + p * 1280 + ks * 32);
                LDSM4(bl, sb_lo + boff + p * 1280 + ks * 32);
                #pragma unroll
                for (int i = 0; i < 4; i++) {
                    float* c0 = acc[i][2 * p];
                    float* c1 = acc[i][2 * p + 1];
                    mma_bf16(c0, ah[i], bh[0], bh[1]);   // hi*hi
                    mma_bf16(c0, ah[i], bl[0], bl[1]);   // hi*lo
                    mma_bf16(c0, al[i], bh[0], bh[1]);   // lo*hi
                    mma_bf16(c1, ah[i], bh[2], bh[3]);
                    mma_bf16(c1, ah[i], bl[2], bl[3]);
                    mma_bf16(c1, al[i], bh[2], bh[3]);
                }
            }
        }

        if (pf) {
            unsigned char* tb = dynsmem + (buf ^ 1) * BUFB;
            #pragma unroll
            for (int op = 0; op < 4; op++) {
                unsigned char* d = tb + op * OPB + sdst_off;
                *(int4*)(d)      = v[op][0];
                *(int4*)(d + 16) = v[op][1];
            }
        }
        __syncthreads();
    }

    // epilogue
    #pragma unroll
    for (int i = 0; i < 4; i++) {
        int r0 = bm + wm * 64 + i * 16 + (lane >> 2);
        #pragma unroll
        for (int n = 0; n < 4; n++) {
            int col = bn + wn * 32 + n * 8 + (lane & 3) * 2;
            *(float2*)(Cout + (size_t)r0 * CDIM + col) =
                make_float2(acc[i][n][0], acc[i][n][1]);
            *(float2*)(Cout + (size_t)(r0 + 8) * CDIM + col) =
                make_float2(acc[i][n][2], acc[i][n][3]);
        }
    }
}

// ---------------------------------------------------------------------------
// RoPE, in place on g_q and g_k.  grid (MROWS, NHEAD), block 64.
// ---------------------------------------------------------------------------
__global__ void rope_kernel(const float* __restrict__ cosp,
                            const float* __restrict__ sinp)
{
    int row = blockIdx.x;            // b*T + t
    int h   = blockIdx.y;
    int i   = threadIdx.x;           // 0..63
    int t   = row & (TSEQ - 1);
    float c = cosp[t * 64 + i];
    float s = sinp[t * 64 + i];
    float* qp = g_q + (size_t)row * CDIM + h * HDIM;
    float* kp = g_k + (size_t)row * CDIM + h * HDIM;
    float q1 = qp[i], q2 = qp[i + 64];
    qp[i]      = q1 * c + q2 * s;
    qp[i + 64] = q1 * c - q2 * s;
    float k1 = kp[i], k2 = kp[i + 64];
    kp[i]      = k1 * c + k2 * s;
    kp[i + 64] = k1 * c - k2 * s;
}

// ---------------------------------------------------------------------------
// Flash attention fp32 (packed-f32x2 MMA loops).  One block = (b, h, q-tile).
// ---------------------------------------------------------------------------
__global__ __launch_bounds__(256, 1)
void flash_kernel()
{
    float* sm = (float*)dynsmem;
    float* QsT = sm;                    // 128*128
    float* KV  = sm + 128 * 128;        // 128*128 (K then V)
    float* St  = sm + 2 * 128 * 128;    // 128*128
    float* m_s = sm + 3 * 128 * 128;    // 128
    float* l_s = m_s + 128;             // 128
    float* c_s = l_s + 128;             // 128

    const int tid = threadIdx.x;
    const int tx  = tid & 15, ty = tid >> 4;
    const int tx4 = tx * 4,  ty4 = ty * 4;
    const int b   = blockIdx.z, h = blockIdx.y;
    const int t0  = blockIdx.x * 128;
    const float scale = 0.08838834764831845f;   // 1/sqrt(128)

    const float* qg = g_q + ((size_t)b * TSEQ + t0) * CDIM + h * HDIM;
    #pragma unroll
    for (int it = 0; it < 16; ++it) {
        int idx = tid + it * 256;
        int mm  = idx >> 5, d4 = idx & 31;
        float4 v = *(const float4*)(qg + (size_t)mm * CDIM + d4 * 4);
        int sw  = (d4 & 7) << 2;
        int mms = mm ^ sw;
        QsT[(d4 * 4 + 0) * 128 + mms] = v.x;
        QsT[(d4 * 4 + 1) * 128 + mms] = v.y;
        QsT[(d4 * 4 + 2) * 128 + mms] = v.z;
        QsT[(d4 * 4 + 3) * 128 + mms] = v.w;
    }
    if (tid < 128) { m_s[tid] = -1e30f; l_s[tid] = 0.f; }

    unsigned long long o2[8][4];
    #pragma unroll
    for (int i = 0; i < 8; i++)
        #pragma unroll
        for (int j = 0; j < 4; j++) o2[i][j] = 0ull;

    __syncthreads();

    for (int kt = 0; kt < TSEQ / 128; ++kt) {
        const float* kg = g_k + ((size_t)b * TSEQ + kt * 128) * CDIM + h * HDIM;
        #pragma unroll
        for (int it = 0; it < 16; ++it) {
            int idx = tid + it * 256;
            int nn  = idx >> 5, d4 = idx & 31;
            float4 v = *(const float4*)(kg + (size_t)nn * CDIM + d4 * 4);
            int sw  = (d4 & 7) << 2;
            int nns = nn ^ sw;
            KV[(d4 * 4 + 0) * 128 + nns] = v.x;
            KV[(d4 * 4 + 1) * 128 + nns] = v.y;
            KV[(d4 * 4 + 2) * 128 + nns] = v.z;
            KV[(d4 * 4 + 3) * 128 + nns] = v.w;
        }
        __syncthreads();

        unsigned long long s2[8][4];
        #pragma unroll
        for (int i = 0; i < 8; i++)
            #pragma unroll
            for (int j = 0; j < 4; j++) s2[i][j] = 0ull;

        #pragma unroll 8
        for (int d = 0; d < 128; ++d) {
            int sw = ((d >> 2) & 7) << 2;
            const float* qr = QsT + d * 128;
            const float* kr = KV  + d * 128;
            float4 a0 = *(const float4*)(qr + (ty4 ^ sw));
            float4 a1 = *(const float4*)(qr + 64 + (ty4 ^ sw));
            ulonglong2 ub0 = *(const ulonglong2*)(kr + (tx4 ^ sw));
            ulonglong2 ub1 = *(const ulonglong2*)(kr + 64 + (tx4 ^ sw));
            unsigned long long bv2[4] = {ub0.x, ub0.y, ub1.x, ub1.y};
            unsigned long long av2[8] = {dup2(a0.x), dup2(a0.y), dup2(a0.z), dup2(a0.w),
                                         dup2(a1.x), dup2(a1.y), dup2(a1.z), dup2(a1.w)};
            #pragma unroll
            for (int i = 0; i < 8; i++)
                #pragma unroll
                for (int j = 0; j < 4; j++)
                    s2[i][j] = fma2(av2[i], bv2[j], s2[i][j]);
        }

        #pragma unroll
        for (int i = 0; i < 8; i++) {
            int m = (i < 4) ? (ty4 + i) : (64 + ty4 + i - 4);
            float sv[8];
            unpack2(s2[i][0], sv[0], sv[1]);
            unpack2(s2[i][1], sv[2], sv[3]);
            unpack2(s2[i][2], sv[4], sv[5]);
            unpack2(s2[i][3], sv[6], sv[7]);
            #pragma unroll
            for (int j = 0; j < 8; j++) {
                int n  = (j < 4) ? (tx4 + j) : (64 + tx4 + j - 4);
                int sw = ((n >> 2) & 7) << 2;
                St[n * 128 + (m ^ sw)] = sv[j] * scale;
            }
        }
        __syncthreads();

        if (tid < 128) {
            int r = tid;
            float mold = m_s[r];
            float mx = mold;
            #pragma unroll 8
            for (int n = 0; n < 128; n++) {
                int sw = ((n >> 2) & 7) << 2;
                mx = fmaxf(mx, St[n * 128 + (r ^ sw)]);
            }
            float corr = __expf(mold - mx);
            float sum = 0.f;
            #pragma unroll 8
            for (int n = 0; n < 128; n++) {
                int sw = ((n >> 2) & 7) << 2;
                float* p = St + n * 128 + (r ^ sw);
                float e = __expf(*p - mx);
                *p = e;
                sum += e;
            }
            m_s[r] = mx;
            l_s[r] = l_s[r] * corr + sum;
            c_s[r] = corr;
        } else {
            const float* vg = g_v + ((size_t)b * TSEQ + kt * 128) * CDIM + h * HDIM;
            #pragma unroll
            for (int it = 0; it < 32; ++it) {
                int idx = (tid - 128) + it * 128;
                int nn  = idx >> 5, c4 = idx & 31;
                float4 v = *(const float4*)(vg + (size_t)nn * CDIM + c4 * 4);
                int sw  = (nn >> 2) & 7;
                *(float4*)(KV + nn * 128 + ((c4 ^ sw) << 2)) = v;
            }
        }
        __syncthreads();

        #pragma unroll
        for (int i = 0; i < 8; i++) {
            int m = (i < 4) ? (ty4 + i) : (64 + ty4 + i - 4);
            unsigned long long crp = dup2(c_s[m]);
            #pragma unroll
            for (int j = 0; j < 4; j++) o2[i][j] = mul2(o2[i][j], crp);
        }

        #pragma unroll 8
        for (int n = 0; n < 128; ++n) {
            int sw = ((n >> 2) & 7) << 2;
            const float* pr = St + n * 128;
            const float* vr = KV + n * 128;
            float4 p0 = *(const float4*)(pr + (ty4 ^ sw));
            float4 p1 = *(const float4*)(pr + 64 + (ty4 ^ sw));
            ulonglong2 uv0 = *(const ulonglong2*)(vr + (tx4 ^ sw));
            ulonglong2 uv1 = *(const ulonglong2*)(vr + 64 + (tx4 ^ sw));
            unsigned long long vv2[4] = {uv0.x, uv0.y, uv1.x, uv1.y};
            unsigned long long pv2[8] = {dup2(p0.x), dup2(p0.y), dup2(p0.z), dup2(p0.w),
                                         dup2(p1.x), dup2(p1.y), dup2(p1.z), dup2(p1.w)};
            #pragma unroll
            for (int i = 0; i < 8; i++)
                #pragma unroll
                for (int j = 0; j < 4; j++)
                    o2[i][j] = fma2(pv2[i], vv2[j], o2[i][j]);
        }
        __syncthreads();
    }

    float* yg = g_y + ((size_t)b * TSEQ + t0) * CDIM + h * HDIM;
    #pragma unroll
    for (int i = 0; i < 8; i++) {
        int m = (i < 4) ? (ty4 + i) : (64 + ty4 + i - 4);
        float inv = 1.0f / l_s[m];
        float r[8];
        unpack2(o2[i][0], r[0], r[1]);
        unpack2(o2[i][1], r[2], r[3]);
        unpack2(o2[i][2], r[4], r[5]);
        unpack2(o2[i][3], r[6], r[7]);
        float4 r0 = make_float4(r[0]*inv, r[1]*inv, r[2]*inv, r[3]*inv);
        float4 r1 = make_float4(r[4]*inv, r[5]*inv, r[6]*inv, r[7]*inv);
        *(float4*)(yg + (size_t)m * CDIM + tx4)      = r0;
        *(float4*)(yg + (size_t)m * CDIM + 64 + tx4) = r1;
    }
}

// ---------------------------------------------------------------------------
extern "C" void kernel_launch(void* const* d_in, const int* in_sizes, int n_in,
                              void* d_out, int out_size)
{
    (void)in_sizes; (void)n_in; (void)out_size;
    const float* x    = (const float*)d_in[0];
    const float* cosp = (const float*)d_in[1];
    const float* sinp = (const float*)d_in[2];
    const float* wq   = (const float*)d_in[3];
    const float* wk   = (const float*)d_in[4];
    const float* wv   = (const float*)d_in[5];
    const float* wo   = (const float*)d_in[6];
    float* out = (float*)d_out;

    float *q, *k, *v, *y;
    __nv_bfloat16 *xhi, *xlo, *yhi, *ylo, *whi, *wlo;
    cudaGetSymbolAddress((void**)&q,   g_q);
    cudaGetSymbolAddress((void**)&k,   g_k);
    cudaGetSymbolAddress((void**)&v,   g_v);
    cudaGetSymbolAddress((void**)&y,   g_y);
    cudaGetSymbolAddress((void**)&xhi, g_xhi);
    cudaGetSymbolAddress((void**)&xlo, g_xlo);
    cudaGetSymbolAddress((void**)&yhi, g_yhi);
    cudaGetSymbolAddress((void**)&ylo, g_ylo);
    cudaGetSymbolAddress((void**)&whi, g_whi);
    cudaGetSymbolAddress((void**)&wlo, g_wlo);

    const size_t W = (size_t)CDIM * CDIM;
    const int n4x = MROWS * CDIM / 4;   // 4,194,304
    const int n4w = CDIM * CDIM / 4;    // 1,048,576

    // split inputs to bf16 hi/lo
    split_kernel<<<n4x / 256, 256>>>(x,  xhi,         xlo,         n4x);
    split_kernel<<<n4w / 256, 256>>>(wq, whi + 0 * W, wlo + 0 * W, n4w);
    split_kernel<<<n4w / 256, 256>>>(wk, whi + 1 * W, wlo + 1 * W, n4w);
    split_kernel<<<n4w / 256, 256>>>(wv, whi + 2 * W, wlo + 2 * W, n4w);
    split_kernel<<<n4w / 256, 256>>>(wo, whi + 3 * W, wlo + 3 * W, n4w);

    cudaFuncSetAttribute(gemm_mma,
                         cudaFuncAttributeMaxDynamicSharedMemorySize, GSMEM);
    dim3 gg(CDIM / 128, MROWS / 128);   // (16, 64) — x fastest keeps A-rows in L2

    gemm_mma<<<gg, 256, GSMEM>>>(xhi, xlo, whi + 0 * W, wlo + 0 * W, q);
    gemm_mma<<<gg, 256, GSMEM>>>(xhi, xlo, whi + 1 * W, wlo + 1 * W, k);
    gemm_mma<<<gg, 256, GSMEM>>>(xhi, xlo, whi + 2 * W, wlo + 2 * W, v);

    rope_kernel<<<dim3(MROWS, NHEAD), 64>>>(cosp, sinp);

    size_t smem = (3 * 128 * 128 + 3 * 128) * sizeof(float);  // 198,144 B
    cudaFuncSetAttribute(flash_kernel,
                         cudaFuncAttributeMaxDynamicSharedMemorySize, (int)smem);
    flash_kernel<<<dim3(TSEQ / 128, NHEAD, BATCH), 256, smem>>>();

    split_kernel<<<n4x / 256, 256>>>(y, yhi, ylo, n4x);
    gemm_mma<<<gg, 256, GSMEM>>>(yhi, ylo, whi + 3 * W, wlo + 3 * W, out);
}

// round 12
// speedup vs baseline: 2.3244x; 1.5736x over previous
#include <cuda_runtime.h>
#include <cuda_bf16.h>
#include <cstdint>

#define BATCH 4
#define TSEQ  2048
#define CDIM  2048
#define NHEAD 16
#define HDIM  128
#define MROWS (BATCH*TSEQ)   // 8192

// ---------------------------------------------------------------------------
// Device-global scratch (no allocations allowed)
// ---------------------------------------------------------------------------
__device__ float g_q[(size_t)MROWS*CDIM];
__device__ float g_k[(size_t)MROWS*CDIM];
__device__ float g_v[(size_t)MROWS*CDIM];
__device__ float g_y[(size_t)MROWS*CDIM];

__device__ __nv_bfloat16 g_xhi[(size_t)MROWS*CDIM];
__device__ __nv_bfloat16 g_xlo[(size_t)MROWS*CDIM];
__device__ __nv_bfloat16 g_yhi[(size_t)MROWS*CDIM];
__device__ __nv_bfloat16 g_ylo[(size_t)MROWS*CDIM];
__device__ __nv_bfloat16 g_whi[4][(size_t)CDIM*CDIM];
__device__ __nv_bfloat16 g_wlo[4][(size_t)CDIM*CDIM];

// bf16 hi/lo for attention operands (post-rope)
__device__ __nv_bfloat16 g_qhi[(size_t)MROWS*CDIM];
__device__ __nv_bfloat16 g_qlo[(size_t)MROWS*CDIM];
__device__ __nv_bfloat16 g_khi[(size_t)MROWS*CDIM];
__device__ __nv_bfloat16 g_klo[(size_t)MROWS*CDIM];
__device__ __nv_bfloat16 g_vhi[(size_t)MROWS*CDIM];
__device__ __nv_bfloat16 g_vlo[(size_t)MROWS*CDIM];

extern __shared__ unsigned char dynsmem[];

// ---------------------------------------------------------------------------
// Helpers
// ---------------------------------------------------------------------------
__device__ __forceinline__ uint32_t smem_u32(const void* p) {
    uint32_t a;
    asm("{ .reg .u64 t; cvta.to.shared.u64 t, %1; cvt.u32.u64 %0, t; }"
        : "=r"(a) : "l"(p));
    return a;
}

#define LDSM4(r, addr) \
    asm volatile("ldmatrix.sync.aligned.m8n8.x4.shared.b16 {%0,%1,%2,%3}, [%4];" \
        : "=r"((r)[0]), "=r"((r)[1]), "=r"((r)[2]), "=r"((r)[3]) : "r"(addr))

#define LDSM4T(r, addr) \
    asm volatile("ldmatrix.sync.aligned.m8n8.x4.trans.shared.b16 {%0,%1,%2,%3}, [%4];" \
        : "=r"((r)[0]), "=r"((r)[1]), "=r"((r)[2]), "=r"((r)[3]) : "r"(addr))

__device__ __forceinline__ void mma_bf16(float* c, const uint32_t* a,
                                         uint32_t b0, uint32_t b1) {
    asm volatile(
        "mma.sync.aligned.m16n8k16.row.col.f32.bf16.bf16.f32 "
        "{%0,%1,%2,%3}, {%4,%5,%6,%7}, {%8,%9}, {%0,%1,%2,%3};"
        : "+f"(c[0]), "+f"(c[1]), "+f"(c[2]), "+f"(c[3])
        : "r"(a[0]), "r"(a[1]), "r"(a[2]), "r"(a[3]), "r"(b0), "r"(b1));
}

__device__ __forceinline__ void cpa16(uint32_t s, const void* g) {
    asm volatile("cp.async.cg.shared.global [%0], [%1], 16;" :: "r"(s), "l"(g));
}
#define CP_COMMIT() asm volatile("cp.async.commit_group;" ::: "memory")
#define CP_WAIT0()  asm volatile("cp.async.wait_group 0;" ::: "memory")

// pack two fp32 -> bf16x2 (lo in low half)
__device__ __forceinline__ uint32_t packbf(float lo, float hi) {
    uint32_t r;
    asm("cvt.rn.bf16x2.f32 %0, %1, %2;" : "=r"(r) : "f"(hi), "f"(lo));
    return r;
}

// ---------------------------------------------------------------------------
// fp32 -> bf16 hi/lo split (2-term), vectorized x4
// ---------------------------------------------------------------------------
__global__ void split_kernel(const float* __restrict__ src,
                             __nv_bfloat16* __restrict__ hi,
                             __nv_bfloat16* __restrict__ lo, int n4)
{
    int i = blockIdx.x * blockDim.x + threadIdx.x;
    if (i >= n4) return;
    float4 v = ((const float4*)src)[i];
    float vv[4] = {v.x, v.y, v.z, v.w};
    unsigned int hw[2], lw[2];
    #pragma unroll
    for (int p = 0; p < 2; p++) {
        float a = vv[2*p], b = vv[2*p+1];
        __nv_bfloat16 ha = __float2bfloat16(a);
        __nv_bfloat16 hb = __float2bfloat16(b);
        __nv_bfloat16 la = __float2bfloat16(a - __bfloat162float(ha));
        __nv_bfloat16 lb = __float2bfloat16(b - __bfloat162float(hb));
        hw[p] = (unsigned)__bfloat16_as_ushort(ha) |
                ((unsigned)__bfloat16_as_ushort(hb) << 16);
        lw[p] = (unsigned)__bfloat16_as_ushort(la) |
                ((unsigned)__bfloat16_as_ushort(lb) << 16);
    }
    ((uint2*)hi)[i] = make_uint2(hw[0], hw[1]);
    ((uint2*)lo)[i] = make_uint2(lw[0], lw[1]);
}

// ---------------------------------------------------------------------------
// mma.sync bf16 split GEMM (unchanged from R11): C[m,n] = sum_k A[m,k]*W[n,k]
// ---------------------------------------------------------------------------
#define OPB   10240          // 128 rows * 80 B
#define BUFB  (4*OPB)
#define GSMEM (2*BUFB)       // 81,920 B

__global__ __launch_bounds__(256)
void gemm_mma(const __nv_bfloat16* __restrict__ Ahi, const __nv_bfloat16* __restrict__ Alo,
              const __nv_bfloat16* __restrict__ Bhi, const __nv_bfloat16* __restrict__ Blo,
              float* __restrict__ Cout)
{
    const int tid  = threadIdx.x;
    const int lane = tid & 31, wid = tid >> 5;
    const int wm   = wid & 1, wn = wid >> 1;
    const int bm   = blockIdx.y * 128, bn = blockIdx.x * 128;

    const int lrow = tid >> 1;
    const int lu   = (tid & 1) * 2;
    const __nv_bfloat16* gsrc[4] = {
        Ahi + (size_t)(bm + lrow) * CDIM + lu * 8,
        Alo + (size_t)(bm + lrow) * CDIM + lu * 8,
        Bhi + (size_t)(bn + lrow) * CDIM + lu * 8,
        Blo + (size_t)(bn + lrow) * CDIM + lu * 8 };
    const uint32_t sdst_off = (uint32_t)(lrow * 80 + lu * 16);

    const int rowA = ((lane >> 3) & 1) * 8 + (lane & 7);
    const uint32_t aoff = (uint32_t)((wm * 64 + rowA) * 80 + (lane >> 4) * 16);
    const int rowB = ((lane >> 4) & 1) * 8 + (lane & 7);
    const uint32_t boff = (uint32_t)((wn * 32 + rowB) * 80 + ((lane >> 3) & 1) * 16);

    float acc[4][4][4];
    #pragma unroll
    for (int i = 0; i < 4; i++)
        #pragma unroll
        for (int n = 0; n < 4; n++)
            #pragma unroll
            for (int r = 0; r < 4; r++) acc[i][n][r] = 0.f;

    const uint32_t sb = smem_u32(dynsmem);

    {
        #pragma unroll
        for (int op = 0; op < 4; op++) {
            int4 v0 = *(const int4*)(gsrc[op]);
            int4 v1 = *(const int4*)(gsrc[op] + 8);
            unsigned char* d = dynsmem + op * OPB + sdst_off;
            *(int4*)(d)      = v0;
            *(int4*)(d + 16) = v1;
        }
    }
    __syncthreads();

    const int NCHUNK = CDIM / 32;
    for (int c = 0; c < NCHUNK; ++c) {
        const int buf = c & 1;
        int4 v[4][2];
        const bool pf = (c + 1 < NCHUNK);
        if (pf) {
            #pragma unroll
            for (int op = 0; op < 4; op++) {
                const __nv_bfloat16* s = gsrc[op] + (c + 1) * 32;
                v[op][0] = *(const int4*)(s);
                v[op][1] = *(const int4*)(s + 8);
            }
        }

        const uint32_t base  = sb + buf * BUFB;
        const uint32_t sa_hi = base;
        const uint32_t sa_lo = base + OPB;
        const uint32_t sb_hi = base + 2 * OPB;
        const uint32_t sb_lo = base + 3 * OPB;

        #pragma unroll
        for (int ks = 0; ks < 2; ++ks) {
            uint32_t ah[4][4], al[4][4];
            #pragma unroll
            for (int i = 0; i < 4; i++) {
                LDSM4(ah[i], sa_hi + aoff + i * 1280 + ks * 32);
                LDSM4(al[i], sa_lo + aoff + i * 1280 + ks * 32);
            }
            #pragma unroll
            for (int p = 0; p < 2; p++) {
                uint32_t bh[4], bl[4];
                LDSM4(bh, sb_hi + boff + p * 1280 + ks * 32);
                LDSM4(bl, sb_lo + boff + p * 1280 + ks * 32);
                #pragma unroll
                for (int i = 0; i < 4; i++) {
                    float* c0 = acc[i][2 * p];
                    float* c1 = acc[i][2 * p + 1];
                    mma_bf16(c0, ah[i], bh[0], bh[1]);
                    mma_bf16(c0, ah[i], bl[0], bl[1]);
                    mma_bf16(c0, al[i], bh[0], bh[1]);
                    mma_bf16(c1, ah[i], bh[2], bh[3]);
                    mma_bf16(c1, ah[i], bl[2], bl[3]);
                    mma_bf16(c1, al[i], bh[2], bh[3]);
                }
            }
        }

        if (pf) {
            unsigned char* tb = dynsmem + (buf ^ 1) * BUFB;
            #pragma unroll
            for (int op = 0; op < 4; op++) {
                unsigned char* d = tb + op * OPB + sdst_off;
                *(int4*)(d)      = v[op][0];
                *(int4*)(d + 16) = v[op][1];
            }
        }
        __syncthreads();
    }

    #pragma unroll
    for (int i = 0; i < 4; i++) {
        int r0 = bm + wm * 64 + i * 16 + (lane >> 2);
        #pragma unroll
        for (int n = 0; n < 4; n++) {
            int col = bn + wn * 32 + n * 8 + (lane & 3) * 2;
            *(float2*)(Cout + (size_t)r0 * CDIM + col) =
                make_float2(acc[i][n][0], acc[i][n][1]);
            *(float2*)(Cout + (size_t)(r0 + 8) * CDIM + col) =
                make_float2(acc[i][n][2], acc[i][n][3]);
        }
    }
}

// ---------------------------------------------------------------------------
// RoPE + bf16 hi/lo split for Q and K.  grid (MROWS, NHEAD), block 64.
// ---------------------------------------------------------------------------
__global__ void rope_split_kernel(const float* __restrict__ cosp,
                                  const float* __restrict__ sinp)
{
    int row = blockIdx.x, h = blockIdx.y, i = threadIdx.x;
    int t   = row & (TSEQ - 1);
    float c = cosp[t * 64 + i];
    float s = sinp[t * 64 + i];
    size_t off = (size_t)row * CDIM + h * HDIM;

    float q1 = g_q[off + i], q2 = g_q[off + i + 64];
    float k1 = g_k[off + i], k2 = g_k[off + i + 64];
    float oq1 = q1 * c + q2 * s, oq2 = q1 * c - q2 * s;
    float ok1 = k1 * c + k2 * s, ok2 = k1 * c - k2 * s;

    __nv_bfloat16 hv;
    hv = __float2bfloat16(oq1); g_qhi[off + i]      = hv; g_qlo[off + i]      = __float2bfloat16(oq1 - __bfloat162float(hv));
    hv = __float2bfloat16(oq2); g_qhi[off + i + 64] = hv; g_qlo[off + i + 64] = __float2bfloat16(oq2 - __bfloat162float(hv));
    hv = __float2bfloat16(ok1); g_khi[off + i]      = hv; g_klo[off + i]      = __float2bfloat16(ok1 - __bfloat162float(hv));
    hv = __float2bfloat16(ok2); g_khi[off + i + 64] = hv; g_klo[off + i + 64] = __float2bfloat16(ok2 - __bfloat162float(hv));
}

// ---------------------------------------------------------------------------
// Flash attention with bf16-split mma.sync.
// Block = (b, h, 128-q-tile), 256 threads, 8 warps; warp owns 16 q-rows.
// BN=64 kv per iter; Q resident in smem; K/V double-buffered via cp.async.
// Smem rows padded to 272 B (17 x 16B units -> conflict-free ldmatrix).
// ---------------------------------------------------------------------------
#define FB_QHI 0
#define FB_QLO 34816
#define FB_KV0 69632
#define FB_OPB 17408          // 64 rows * 272
#define FB_BUF 69632          // Khi,Klo,Vhi,Vlo
#define FSMEM  208896         // Q + 2 KV buffers

__global__ __launch_bounds__(256, 1)
void flash_mma()
{
    const int tid = threadIdx.x, lane = tid & 31, w = tid >> 5;
    const int b = blockIdx.z, h = blockIdx.y;
    const int t0 = blockIdx.x * 128;
    const uint32_t sb = smem_u32(dynsmem);
    const float alpha = 0.1275174293f;     // (1/sqrt(128)) * log2(e)

    // ---- Q tile (hi/lo) via cp.async ----
    {
        int row = tid >> 1, half = tid & 1;
        size_t g = ((size_t)(b * TSEQ + t0 + row)) * CDIM + h * HDIM + half * 64;
        uint32_t dh = sb + FB_QHI + row * 272 + half * 128;
        uint32_t dl = sb + FB_QLO + row * 272 + half * 128;
        #pragma unroll
        for (int i = 0; i < 8; i++) {
            cpa16(dh + i * 16, g_qhi + g + i * 8);
            cpa16(dl + i * 16, g_qlo + g + i * 8);
        }
    }
    // ---- KV tile 0 ----
    {
        int row = tid >> 2, seg = tid & 3;
        size_t g = ((size_t)(b * TSEQ + row)) * CDIM + h * HDIM + seg * 32;
        uint32_t d = sb + FB_KV0 + row * 272 + seg * 64;
        #pragma unroll
        for (int i = 0; i < 4; i++) {
            cpa16(d + 0 * FB_OPB + i * 16, g_khi + g + i * 8);
            cpa16(d + 1 * FB_OPB + i * 16, g_klo + g + i * 8);
            cpa16(d + 2 * FB_OPB + i * 16, g_vhi + g + i * 8);
            cpa16(d + 3 * FB_OPB + i * 16, g_vlo + g + i * 8);
        }
    }
    CP_COMMIT(); CP_WAIT0(); __syncthreads();

    // fragment address bases
    const uint32_t a_off = (uint32_t)((w * 16 + (lane & 15)) * 272 + (lane >> 4) * 16);
    const uint32_t aq_hi = sb + FB_QHI + a_off;
    const uint32_t aq_lo = sb + FB_QLO + a_off;
    const uint32_t b_off = (uint32_t)((((lane >> 4) & 1) * 8 + (lane & 7)) * 272
                                      + ((lane >> 3) & 1) * 16);
    const uint32_t v_off = (uint32_t)((lane & 15) * 272 + (lane >> 4) * 16);

    float o[16][4];
    #pragma unroll
    for (int q = 0; q < 16; q++)
        #pragma unroll
        for (int r = 0; r < 4; r++) o[q][r] = 0.f;
    float mr0 = -1e30f, mr1 = -1e30f, lr0 = 0.f, lr1 = 0.f;

    const int NIT = TSEQ / 64;   // 32
    for (int c = 0; c < NIT; ++c) {
        const int buf = c & 1;
        if (c + 1 < NIT) {       // prefetch next KV into other buffer
            int row = tid >> 2, seg = tid & 3;
            size_t g = ((size_t)(b * TSEQ + (c + 1) * 64 + row)) * CDIM + h * HDIM + seg * 32;
            uint32_t d = sb + FB_KV0 + (buf ^ 1) * FB_BUF + row * 272 + seg * 64;
            #pragma unroll
            for (int i = 0; i < 4; i++) {
                cpa16(d + 0 * FB_OPB + i * 16, g_khi + g + i * 8);
                cpa16(d + 1 * FB_OPB + i * 16, g_klo + g + i * 8);
                cpa16(d + 2 * FB_OPB + i * 16, g_vhi + g + i * 8);
                cpa16(d + 3 * FB_OPB + i * 16, g_vlo + g + i * 8);
            }
        }
        CP_COMMIT();

        const uint32_t kb_hi = sb + FB_KV0 + buf * FB_BUF;
        const uint32_t kb_lo = kb_hi + FB_OPB;
        const uint32_t vb_hi = kb_hi + 2 * FB_OPB;
        const uint32_t vb_lo = kb_hi + 3 * FB_OPB;

        // ---- S = Q K^T (3-term split) ----
        float s[8][4];
        #pragma unroll
        for (int a = 0; a < 8; a++)
            #pragma unroll
            for (int r = 0; r < 4; r++) s[a][r] = 0.f;

        #pragma unroll
        for (int ks = 0; ks < 8; ks++) {
            uint32_t ah[4], al[4];
            LDSM4(ah, aq_hi + ks * 32);
            LDSM4(al, aq_lo + ks * 32);
            #pragma unroll
            for (int p = 0; p < 4; p++) {
                uint32_t bh[4], bl[4];
                LDSM4(bh, kb_hi + b_off + p * (16 * 272) + ks * 32);
                LDSM4(bl, kb_lo + b_off + p * (16 * 272) + ks * 32);
                mma_bf16(s[2*p],   ah, bh[0], bh[1]);
                mma_bf16(s[2*p+1], ah, bh[2], bh[3]);
                mma_bf16(s[2*p],   ah, bl[0], bl[1]);
                mma_bf16(s[2*p+1], ah, bl[2], bl[3]);
                mma_bf16(s[2*p],   al, bh[0], bh[1]);
                mma_bf16(s[2*p+1], al, bh[2], bh[3]);
            }
        }

        // ---- online softmax (per-thread rows lane>>2 and lane>>2+8) ----
        float mx0 = s[0][0], mx1 = s[0][2];
        #pragma unroll
        for (int a = 0; a < 8; a++) {
            mx0 = fmaxf(mx0, fmaxf(s[a][0], s[a][1]));
            mx1 = fmaxf(mx1, fmaxf(s[a][2], s[a][3]));
        }
        mx0 = fmaxf(mx0, __shfl_xor_sync(0xFFFFFFFFu, mx0, 1));
        mx0 = fmaxf(mx0, __shfl_xor_sync(0xFFFFFFFFu, mx0, 2));
        mx1 = fmaxf(mx1, __shfl_xor_sync(0xFFFFFFFFu, mx1, 1));
        mx1 = fmaxf(mx1, __shfl_xor_sync(0xFFFFFFFFu, mx1, 2));
        float mn0 = fmaxf(mr0, mx0), mn1 = fmaxf(mr1, mx1);
        float corr0 = exp2f((mr0 - mn0) * alpha);
        float corr1 = exp2f((mr1 - mn1) * alpha);
        float sum0 = 0.f, sum1 = 0.f;
        #pragma unroll
        for (int a = 0; a < 8; a++) {
            s[a][0] = exp2f((s[a][0] - mn0) * alpha);
            s[a][1] = exp2f((s[a][1] - mn0) * alpha);
            s[a][2] = exp2f((s[a][2] - mn1) * alpha);
            s[a][3] = exp2f((s[a][3] - mn1) * alpha);
            sum0 += s[a][0] + s[a][1];
            sum1 += s[a][2] + s[a][3];
        }
        sum0 += __shfl_xor_sync(0xFFFFFFFFu, sum0, 1);
        sum0 += __shfl_xor_sync(0xFFFFFFFFu, sum0, 2);
        sum1 += __shfl_xor_sync(0xFFFFFFFFu, sum1, 1);
        sum1 += __shfl_xor_sync(0xFFFFFFFFu, sum1, 2);
        lr0 = lr0 * corr0 + sum0;
        lr1 = lr1 * corr1 + sum1;
        mr0 = mn0; mr1 = mn1;
        #pragma unroll
        for (int q = 0; q < 16; q++) {
            o[q][0] *= corr0; o[q][1] *= corr0;
            o[q][2] *= corr1; o[q][3] *= corr1;
        }

        // ---- pack P into A-fragments (hi + residual lo), pure registers ----
        uint32_t ph[8][2], pl[8][2];
        #pragma unroll
        for (int a = 0; a < 8; a++) {
            float p0 = s[a][0], p1 = s[a][1], p2 = s[a][2], p3 = s[a][3];
            ph[a][0] = packbf(p0, p1);
            ph[a][1] = packbf(p2, p3);
            float r0 = p0 - __bfloat162float(__float2bfloat16(p0));
            float r1 = p1 - __bfloat162float(__float2bfloat16(p1));
            float r2 = p2 - __bfloat162float(__float2bfloat16(p2));
            float r3 = p3 - __bfloat162float(__float2bfloat16(p3));
            pl[a][0] = packbf(r0, r1);
            pl[a][1] = packbf(r2, r3);
        }

        // ---- O += P V (3-term split, V transposed via ldmatrix.trans) ----
        #pragma unroll
        for (int kk = 0; kk < 4; kk++) {
            uint32_t ahh[4] = {ph[2*kk][0], ph[2*kk][1], ph[2*kk+1][0], ph[2*kk+1][1]};
            uint32_t ahl[4] = {pl[2*kk][0], pl[2*kk][1], pl[2*kk+1][0], pl[2*kk+1][1]};
            #pragma unroll
            for (int q = 0; q < 8; q++) {
                uint32_t vh[4], vl[4];
                LDSM4T(vh, vb_hi + v_off + kk * (16 * 272) + q * 32);
                LDSM4T(vl, vb_lo + v_off + kk * (16 * 272) + q * 32);
                mma_bf16(o[2*q],   ahh, vh[0], vh[1]);
                mma_bf16(o[2*q+1], ahh, vh[2], vh[3]);
                mma_bf16(o[2*q],   ahh, vl[0], vl[1]);
                mma_bf16(o[2*q+1], ahh, vl[2], vl[3]);
                mma_bf16(o[2*q],   ahl, vh[0], vh[1]);
                mma_bf16(o[2*q+1], ahl, vh[2], vh[3]);
            }
        }
        CP_WAIT0(); __syncthreads();
    }

    // ---- epilogue: O /= l ----
    float i0 = 1.f / lr0, i1 = 1.f / lr1;
    int r0 = t0 + w * 16 + (lane >> 2);
    size_t base0 = ((size_t)(b * TSEQ + r0)) * CDIM + h * HDIM + (lane & 3) * 2;
    size_t base1 = base0 + (size_t)8 * CDIM;
    #pragma unroll
    for (int q = 0; q < 16; q++) {
        *(float2*)(g_y + base0 + q * 8) = make_float2(o[q][0] * i0, o[q][1] * i0);
        *(float2*)(g_y + base1 + q * 8) = make_float2(o[q][2] * i1, o[q][3] * i1);
    }
}

// ---------------------------------------------------------------------------
extern "C" void kernel_launch(void* const* d_in, const int* in_sizes, int n_in,
                              void* d_out, int out_size)
{
    (void)in_sizes; (void)n_in; (void)out_size;
    const float* x    = (const float*)d_in[0];
    const float* cosp = (const float*)d_in[1];
    const float* sinp = (const float*)d_in[2];
    const float* wq   = (const float*)d_in[3];
    const float* wk   = (const float*)d_in[4];
    const float* wv   = (const float*)d_in[5];
    const float* wo   = (const float*)d_in[6];
    float* out = (float*)d_out;

    float *q, *k, *v, *y;
    __nv_bfloat16 *xhi, *xlo, *yhi, *ylo, *whi, *wlo, *vhi, *vlo;
    cudaGetSymbolAddress((void**)&q,   g_q);
    cudaGetSymbolAddress((void**)&k,   g_k);
    cudaGetSymbolAddress((void**)&v,   g_v);
    cudaGetSymbolAddress((void**)&y,   g_y);
    cudaGetSymbolAddress((void**)&xhi, g_xhi);
    cudaGetSymbolAddress((void**)&xlo, g_xlo);
    cudaGetSymbolAddress((void**)&yhi, g_yhi);
    cudaGetSymbolAddress((void**)&ylo, g_ylo);
    cudaGetSymbolAddress((void**)&whi, g_whi);
    cudaGetSymbolAddress((void**)&wlo, g_wlo);
    cudaGetSymbolAddress((void**)&vhi, g_vhi);
    cudaGetSymbolAddress((void**)&vlo, g_vlo);

    const size_t W = (size_t)CDIM * CDIM;
    const int n4x = MROWS * CDIM / 4;
    const int n4w = CDIM * CDIM / 4;

    split_kernel<<<n4x / 256, 256>>>(x,  xhi,         xlo,         n4x);
    split_kernel<<<n4w / 256, 256>>>(wq, whi + 0 * W, wlo + 0 * W, n4w);
    split_kernel<<<n4w / 256, 256>>>(wk, whi + 1 * W, wlo + 1 * W, n4w);
    split_kernel<<<n4w / 256, 256>>>(wv, whi + 2 * W, wlo + 2 * W, n4w);
    split_kernel<<<n4w / 256, 256>>>(wo, whi + 3 * W, wlo + 3 * W, n4w);

    cudaFuncSetAttribute(gemm_mma,
                         cudaFuncAttributeMaxDynamicSharedMemorySize, GSMEM);
    dim3 gg(CDIM / 128, MROWS / 128);

    gemm_mma<<<gg, 256, GSMEM>>>(xhi, xlo, whi + 0 * W, wlo + 0 * W, q);
    gemm_mma<<<gg, 256, GSMEM>>>(xhi, xlo, whi + 1 * W, wlo + 1 * W, k);
    gemm_mma<<<gg, 256, GSMEM>>>(xhi, xlo, whi + 2 * W, wlo + 2 * W, v);

    rope_split_kernel<<<dim3(MROWS, NHEAD), 64>>>(cosp, sinp);
    split_kernel<<<n4x / 256, 256>>>(v, vhi, vlo, n4x);

    cudaFuncSetAttribute(flash_mma,
                         cudaFuncAttributeMaxDynamicSharedMemorySize, FSMEM);
    flash_mma<<<dim3(TSEQ / 128, NHEAD, BATCH), 256, FSMEM>>>();

    split_kernel<<<n4x / 256, 256>>>(y, yhi, ylo, n4x);
    gemm_mma<<<gg, 256, GSMEM>>>(yhi, ylo, whi + 3 * W, wlo + 3 * W, out);
}

// round 13
// speedup vs baseline: 2.4467x; 1.0526x over previous
#include <cuda_runtime.h>
#include <cuda_bf16.h>
#include <cstdint>

#define BATCH 4
#define TSEQ  2048
#define CDIM  2048
#define NHEAD 16
#define HDIM  128
#define MROWS (BATCH*TSEQ)   // 8192

// ---------------------------------------------------------------------------
// Device-global scratch (no allocations allowed)
// ---------------------------------------------------------------------------
__device__ __nv_bfloat16 g_xhi[(size_t)MROWS*CDIM];
__device__ __nv_bfloat16 g_xlo[(size_t)MROWS*CDIM];
__device__ __nv_bfloat16 g_yhi[(size_t)MROWS*CDIM];
__device__ __nv_bfloat16 g_ylo[(size_t)MROWS*CDIM];
__device__ __nv_bfloat16 g_whi[4][(size_t)CDIM*CDIM];
__device__ __nv_bfloat16 g_wlo[4][(size_t)CDIM*CDIM];

// attention operands (q/k in rope-pair-permuted d-layout; v in true layout)
__device__ __nv_bfloat16 g_qhi[(size_t)MROWS*CDIM];
__device__ __nv_bfloat16 g_qlo[(size_t)MROWS*CDIM];
__device__ __nv_bfloat16 g_khi[(size_t)MROWS*CDIM];
__device__ __nv_bfloat16 g_klo[(size_t)MROWS*CDIM];
__device__ __nv_bfloat16 g_vhi[(size_t)MROWS*CDIM];
__device__ __nv_bfloat16 g_vlo[(size_t)MROWS*CDIM];

extern __shared__ unsigned char dynsmem[];

// ---------------------------------------------------------------------------
// Helpers
// ---------------------------------------------------------------------------
__device__ __forceinline__ uint32_t smem_u32(const void* p) {
    uint32_t a;
    asm("{ .reg .u64 t; cvta.to.shared.u64 t, %1; cvt.u32.u64 %0, t; }"
        : "=r"(a) : "l"(p));
    return a;
}

#define LDSM4(r, addr) \
    asm volatile("ldmatrix.sync.aligned.m8n8.x4.shared.b16 {%0,%1,%2,%3}, [%4];" \
        : "=r"((r)[0]), "=r"((r)[1]), "=r"((r)[2]), "=r"((r)[3]) : "r"(addr))

#define LDSM4T(r, addr) \
    asm volatile("ldmatrix.sync.aligned.m8n8.x4.trans.shared.b16 {%0,%1,%2,%3}, [%4];" \
        : "=r"((r)[0]), "=r"((r)[1]), "=r"((r)[2]), "=r"((r)[3]) : "r"(addr))

__device__ __forceinline__ void mma_bf16(float* c, const uint32_t* a,
                                         uint32_t b0, uint32_t b1) {
    asm volatile(
        "mma.sync.aligned.m16n8k16.row.col.f32.bf16.bf16.f32 "
        "{%0,%1,%2,%3}, {%4,%5,%6,%7}, {%8,%9}, {%0,%1,%2,%3};"
        : "+f"(c[0]), "+f"(c[1]), "+f"(c[2]), "+f"(c[3])
        : "r"(a[0]), "r"(a[1]), "r"(a[2]), "r"(a[3]), "r"(b0), "r"(b1));
}

__device__ __forceinline__ void cpa16(uint32_t s, const void* g) {
    asm volatile("cp.async.cg.shared.global [%0], [%1], 16;" :: "r"(s), "l"(g));
}
#define CP_COMMIT() asm volatile("cp.async.commit_group;" ::: "memory")
#define CP_WAIT0()  asm volatile("cp.async.wait_group 0;" ::: "memory")
#define CP_WAIT1()  asm volatile("cp.async.wait_group 1;" ::: "memory")

// pack two fp32 -> bf16x2 (a in low half)
__device__ __forceinline__ uint32_t packbf(float a, float b) {
    uint32_t r;
    asm("cvt.rn.bf16x2.f32 %0, %1, %2;" : "=r"(r) : "f"(b), "f"(a));
    return r;
}

// split pair (a,b) into bf16x2 hi word + bf16x2 residual word
__device__ __forceinline__ void split2(float a, float b, uint32_t& hi, uint32_t& lo) {
    __nv_bfloat16 ha = __float2bfloat16(a), hb = __float2bfloat16(b);
    float ra = a - __bfloat162float(ha), rb = b - __bfloat162float(hb);
    hi = (uint32_t)__bfloat16_as_ushort(ha) |
         ((uint32_t)__bfloat16_as_ushort(hb) << 16);
    lo = (uint32_t)__bfloat16_as_ushort(__float2bfloat16(ra)) |
         ((uint32_t)__bfloat16_as_ushort(__float2bfloat16(rb)) << 16);
}

// ---------------------------------------------------------------------------
// fp32 -> bf16 hi/lo split (for x and weights)
// ---------------------------------------------------------------------------
__global__ void split_kernel(const float* __restrict__ src,
                             __nv_bfloat16* __restrict__ hi,
                             __nv_bfloat16* __restrict__ lo, int n4)
{
    int i = blockIdx.x * blockDim.x + threadIdx.x;
    if (i >= n4) return;
    float4 v = ((const float4*)src)[i];
    float vv[4] = {v.x, v.y, v.z, v.w};
    unsigned int hw[2], lw[2];
    #pragma unroll
    for (int p = 0; p < 2; p++) {
        split2(vv[2*p], vv[2*p+1], hw[p], lw[p]);
    }
    ((uint2*)hi)[i] = make_uint2(hw[0], hw[1]);
    ((uint2*)lo)[i] = make_uint2(lw[0], lw[1]);
}

// ---------------------------------------------------------------------------
// Fused bf16-split GEMM: C[m,n] = sum_k A[m,k]*W[n,k]
// 128(M) x 256(N) x 32(K) CTA tile, 8 warps (2M x 4N, 64x64 warp tile),
// cp.async 3-stage pipeline, 80B-padded K-major smem rows.
// stage==0: A=x, W=w[z] (z=blockIdx.z). z<2 -> rope+split epilogue into
//           permuted-layout q/k; z==2 -> split epilogue into v.
// stage==1: A=y(bf16), W=w[3], float epilogue into out.
// ---------------------------------------------------------------------------
#define GA_HI  0
#define GA_LO  10240
#define GB_HI  20480
#define GB_LO  40960
#define GSTAGE 61440
#define GSMEM3 184320

__global__ __launch_bounds__(256)
void gemm_fused(int stage, const float* __restrict__ cosp,
                const float* __restrict__ sinp, float* __restrict__ out)
{
    const int tid = threadIdx.x, lane = tid & 31, wid = tid >> 5;
    const int wm = wid & 1, wn = wid >> 1;
    const int bm = blockIdx.y * 128, bn = blockIdx.x * 256;
    const int z  = stage ? 3 : blockIdx.z;
    const bool perm = (stage == 0) && (z < 2);

    const __nv_bfloat16* Ah = stage ? g_yhi : g_xhi;
    const __nv_bfloat16* Al = stage ? g_ylo : g_xlo;
    const __nv_bfloat16* Wh = g_whi[z];
    const __nv_bfloat16* Wl = g_wlo[z];

    const uint32_t sb = smem_u32(dynsmem);

    // stage loader (cp.async): A 1024 chunks, B 2048 chunks of 16B
    auto load_stage = [&](int c, int buf) {
        const int kb = c * 32;
        const uint32_t sbb = sb + buf * GSTAGE;
        #pragma unroll
        for (int i = 0; i < 4; i++) {
            int id = i * 256 + tid;
            int rr = id >> 2, seg = id & 3;
            bool hi = rr < 128; int row = rr & 127;
            const __nv_bfloat16* src = (hi ? Ah : Al)
                + (size_t)(bm + row) * CDIM + kb + seg * 8;
            cpa16(sbb + (hi ? GA_HI : GA_LO) + row * 80 + seg * 16, src);
        }
        #pragma unroll
        for (int i = 0; i < 8; i++) {
            int id = i * 256 + tid;
            int rr = id >> 2, seg = id & 3;
            bool hi = rr < 256; int row = rr & 255;
            int cc = bn + row;
            int tc = perm ? ((cc & ~127) | ((cc & 127) >> 1) | ((cc & 1) << 6)) : cc;
            const __nv_bfloat16* src = (hi ? Wh : Wl)
                + (size_t)tc * CDIM + kb + seg * 8;
            cpa16(sbb + (hi ? GB_HI : GB_LO) + row * 80 + seg * 16, src);
        }
        CP_COMMIT();
    };

    float acc[4][8][4];
    #pragma unroll
    for (int i = 0; i < 4; i++)
        #pragma unroll
        for (int n = 0; n < 8; n++)
            #pragma unroll
            for (int r = 0; r < 4; r++) acc[i][n][r] = 0.f;

    const int rowA = ((lane >> 3) & 1) * 8 + (lane & 7);
    const uint32_t akh = (uint32_t)((wm * 64 + rowA) * 80 + (lane >> 4) * 16);
    const int rowB = ((lane >> 4) & 1) * 8 + (lane & 7);
    const uint32_t bkh = (uint32_t)((wn * 64 + rowB) * 80 + ((lane >> 3) & 1) * 16);

    const int NC = CDIM / 32;   // 64
    load_stage(0, 0);
    load_stage(1, 1);

    for (int c = 0; c < NC; ++c) {
        CP_WAIT1();             // stage c arrived (allow 1 pending)
        __syncthreads();
        if (c + 2 < NC) load_stage(c + 2, (c + 2) % 3);

        const uint32_t base = sb + (c % 3) * GSTAGE;
        #pragma unroll
        for (int ks = 0; ks < 2; ++ks) {
            uint32_t ah[4][4], al[4][4];
            #pragma unroll
            for (int i = 0; i < 4; i++) {
                LDSM4(ah[i], base + GA_HI + akh + i * 1280 + ks * 32);
                LDSM4(al[i], base + GA_LO + akh + i * 1280 + ks * 32);
            }
            #pragma unroll
            for (int p = 0; p < 4; p++) {
                uint32_t bh[4], bl[4];
                LDSM4(bh, base + GB_HI + bkh + p * 1280 + ks * 32);
                LDSM4(bl, base + GB_LO + bkh + p * 1280 + ks * 32);
                #pragma unroll
                for (int i = 0; i < 4; i++) {
                    float* c0 = acc[i][2 * p];
                    float* c1 = acc[i][2 * p + 1];
                    mma_bf16(c0, ah[i], bh[0], bh[1]);
                    mma_bf16(c0, ah[i], bl[0], bl[1]);
                    mma_bf16(c0, al[i], bh[0], bh[1]);
                    mma_bf16(c1, ah[i], bh[2], bh[3]);
                    mma_bf16(c1, ah[i], bl[2], bl[3]);
                    mma_bf16(c1, al[i], bh[2], bh[3]);
                }
            }
        }
        __syncthreads();
    }

    // ---- epilogue ----
    if (stage == 0 && z < 2) {
        __nv_bfloat16* dh = z ? g_khi : g_qhi;
        __nv_bfloat16* dl = z ? g_klo : g_qlo;
        #pragma unroll
        for (int i = 0; i < 4; i++) {
            int r0 = bm + wm * 64 + i * 16 + (lane >> 2);
            int r1 = r0 + 8;
            int ti0 = (r0 & (TSEQ - 1)) * 64;
            int ti1 = (r1 & (TSEQ - 1)) * 64;
            #pragma unroll
            for (int n = 0; n < 8; n++) {
                int S0 = bn + wn * 64 + n * 8 + (lane & 3) * 2;
                int t  = (S0 & 127) >> 1;
                float c0 = cosp[ti0 + t], s0 = sinp[ti0 + t];
                float c1 = cosp[ti1 + t], s1 = sinp[ti1 + t];
                uint32_t hh, ll;
                float x1 = acc[i][n][0], x2 = acc[i][n][1];
                split2(x1 * c0 + x2 * s0, x1 * c0 - x2 * s0, hh, ll);
                *(uint32_t*)(dh + (size_t)r0 * CDIM + S0) = hh;
                *(uint32_t*)(dl + (size_t)r0 * CDIM + S0) = ll;
                x1 = acc[i][n][2]; x2 = acc[i][n][3];
                split2(x1 * c1 + x2 * s1, x1 * c1 - x2 * s1, hh, ll);
                *(uint32_t*)(dh + (size_t)r1 * CDIM + S0) = hh;
                *(uint32_t*)(dl + (size_t)r1 * CDIM + S0) = ll;
            }
        }
    } else if (stage == 0) {   // z == 2 : V
        #pragma unroll
        for (int i = 0; i < 4; i++) {
            int r0 = bm + wm * 64 + i * 16 + (lane >> 2);
            int r1 = r0 + 8;
            #pragma unroll
            for (int n = 0; n < 8; n++) {
                int S0 = bn + wn * 64 + n * 8 + (lane & 3) * 2;
                uint32_t hh, ll;
                split2(acc[i][n][0], acc[i][n][1], hh, ll);
                *(uint32_t*)(g_vhi + (size_t)r0 * CDIM + S0) = hh;
                *(uint32_t*)(g_vlo + (size_t)r0 * CDIM + S0) = ll;
                split2(acc[i][n][2], acc[i][n][3], hh, ll);
                *(uint32_t*)(g_vhi + (size_t)r1 * CDIM + S0) = hh;
                *(uint32_t*)(g_vlo + (size_t)r1 * CDIM + S0) = ll;
            }
        }
    } else {                    // WO: float out
        #pragma unroll
        for (int i = 0; i < 4; i++) {
            int r0 = bm + wm * 64 + i * 16 + (lane >> 2);
            int r1 = r0 + 8;
            #pragma unroll
            for (int n = 0; n < 8; n++) {
                int S0 = bn + wn * 64 + n * 8 + (lane & 3) * 2;
                *(float2*)(out + (size_t)r0 * CDIM + S0) =
                    make_float2(acc[i][n][0], acc[i][n][1]);
                *(float2*)(out + (size_t)r1 * CDIM + S0) =
                    make_float2(acc[i][n][2], acc[i][n][3]);
            }
        }
    }
}

// ---------------------------------------------------------------------------
// Flash attention with bf16-split mma.sync (R12-proven core).
// Block = (b, h, 128-q-tile), 256 threads, 8 warps; warp owns 16 q-rows.
// BN=64 kv per iter; Q resident; K/V double-buffered via cp.async.
// Epilogue writes yhi/ylo bf16 directly.
// ---------------------------------------------------------------------------
#define FB_QHI 0
#define FB_QLO 34816
#define FB_KV0 69632
#define FB_OPB 17408          // 64 rows * 272
#define FB_BUF 69632          // Khi,Klo,Vhi,Vlo
#define FSMEM  208896

__global__ __launch_bounds__(256, 1)
void flash_mma()
{
    const int tid = threadIdx.x, lane = tid & 31, w = tid >> 5;
    const int b = blockIdx.z, h = blockIdx.y;
    const int t0 = blockIdx.x * 128;
    const uint32_t sb = smem_u32(dynsmem);
    const float alpha = 0.1275174293f;     // (1/sqrt(128)) * log2(e)

    {   // Q tile (hi/lo)
        int row = tid >> 1, half = tid & 1;
        size_t g = ((size_t)(b * TSEQ + t0 + row)) * CDIM + h * HDIM + half * 64;
        uint32_t dh = sb + FB_QHI + row * 272 + half * 128;
        uint32_t dl = sb + FB_QLO + row * 272 + half * 128;
        #pragma unroll
        for (int i = 0; i < 8; i++) {
            cpa16(dh + i * 16, g_qhi + g + i * 8);
            cpa16(dl + i * 16, g_qlo + g + i * 8);
        }
    }
    {   // KV tile 0
        int row = tid >> 2, seg = tid & 3;
        size_t g = ((size_t)(b * TSEQ + row)) * CDIM + h * HDIM + seg * 32;
        uint32_t d = sb + FB_KV0 + row * 272 + seg * 64;
        #pragma unroll
        for (int i = 0; i < 4; i++) {
            cpa16(d + 0 * FB_OPB + i * 16, g_khi + g + i * 8);
            cpa16(d + 1 * FB_OPB + i * 16, g_klo + g + i * 8);
            cpa16(d + 2 * FB_OPB + i * 16, g_vhi + g + i * 8);
            cpa16(d + 3 * FB_OPB + i * 16, g_vlo + g + i * 8);
        }
    }
    CP_COMMIT(); CP_WAIT0(); __syncthreads();

    const uint32_t a_off = (uint32_t)((w * 16 + (lane & 15)) * 272 + (lane >> 4) * 16);
    const uint32_t aq_hi = sb + FB_QHI + a_off;
    const uint32_t aq_lo = sb + FB_QLO + a_off;
    const uint32_t b_off = (uint32_t)((((lane >> 4) & 1) * 8 + (lane & 7)) * 272
                                      + ((lane >> 3) & 1) * 16);
    const uint32_t v_off = (uint32_t)((lane & 15) * 272 + (lane >> 4) * 16);

    float o[16][4];
    #pragma unroll
    for (int q = 0; q < 16; q++)
        #pragma unroll
        for (int r = 0; r < 4; r++) o[q][r] = 0.f;
    float mr0 = -1e30f, mr1 = -1e30f, lr0 = 0.f, lr1 = 0.f;

    const int NIT = TSEQ / 64;
    for (int c = 0; c < NIT; ++c) {
        const int buf = c & 1;
        if (c + 1 < NIT) {
            int row = tid >> 2, seg = tid & 3;
            size_t g = ((size_t)(b * TSEQ + (c + 1) * 64 + row)) * CDIM + h * HDIM + seg * 32;
            uint32_t d = sb + FB_KV0 + (buf ^ 1) * FB_BUF + row * 272 + seg * 64;
            #pragma unroll
            for (int i = 0; i < 4; i++) {
                cpa16(d + 0 * FB_OPB + i * 16, g_khi + g + i * 8);
                cpa16(d + 1 * FB_OPB + i * 16, g_klo + g + i * 8);
                cpa16(d + 2 * FB_OPB + i * 16, g_vhi + g + i * 8);
                cpa16(d + 3 * FB_OPB + i * 16, g_vlo + g + i * 8);
            }
        }
        CP_COMMIT();

        const uint32_t kb_hi = sb + FB_KV0 + buf * FB_BUF;
        const uint32_t kb_lo = kb_hi + FB_OPB;
        const uint32_t vb_hi = kb_hi + 2 * FB_OPB;
        const uint32_t vb_lo = kb_hi + 3 * FB_OPB;

        float s[8][4];
        #pragma unroll
        for (int a = 0; a < 8; a++)
            #pragma unroll
            for (int r = 0; r < 4; r++) s[a][r] = 0.f;

        #pragma unroll
        for (int ks = 0; ks < 8; ks++) {
            uint32_t ah[4], al[4];
            LDSM4(ah, aq_hi + ks * 32);
            LDSM4(al, aq_lo + ks * 32);
            #pragma unroll
            for (int p = 0; p < 4; p++) {
                uint32_t bh[4], bl[4];
                LDSM4(bh, kb_hi + b_off + p * (16 * 272) + ks * 32);
                LDSM4(bl, kb_lo + b_off + p * (16 * 272) + ks * 32);
                mma_bf16(s[2*p],   ah, bh[0], bh[1]);
                mma_bf16(s[2*p+1], ah, bh[2], bh[3]);
                mma_bf16(s[2*p],   ah, bl[0], bl[1]);
                mma_bf16(s[2*p+1], ah, bl[2], bl[3]);
                mma_bf16(s[2*p],   al, bh[0], bh[1]);
                mma_bf16(s[2*p+1], al, bh[2], bh[3]);
            }
        }

        float mx0 = s[0][0], mx1 = s[0][2];
        #pragma unroll
        for (int a = 0; a < 8; a++) {
            mx0 = fmaxf(mx0, fmaxf(s[a][0], s[a][1]));
            mx1 = fmaxf(mx1, fmaxf(s[a][2], s[a][3]));
        }
        mx0 = fmaxf(mx0, __shfl_xor_sync(0xFFFFFFFFu, mx0, 1));
        mx0 = fmaxf(mx0, __shfl_xor_sync(0xFFFFFFFFu, mx0, 2));
        mx1 = fmaxf(mx1, __shfl_xor_sync(0xFFFFFFFFu, mx1, 1));
        mx1 = fmaxf(mx1, __shfl_xor_sync(0xFFFFFFFFu, mx1, 2));
        float mn0 = fmaxf(mr0, mx0), mn1 = fmaxf(mr1, mx1);
        float corr0 = exp2f((mr0 - mn0) * alpha);
        float corr1 = exp2f((mr1 - mn1) * alpha);
        float sum0 = 0.f, sum1 = 0.f;
        #pragma unroll
        for (int a = 0; a < 8; a++) {
            s[a][0] = exp2f((s[a][0] - mn0) * alpha);
            s[a][1] = exp2f((s[a][1] - mn0) * alpha);
            s[a][2] = exp2f((s[a][2] - mn1) * alpha);
            s[a][3] = exp2f((s[a][3] - mn1) * alpha);
            sum0 += s[a][0] + s[a][1];
            sum1 += s[a][2] + s[a][3];
        }
        sum0 += __shfl_xor_sync(0xFFFFFFFFu, sum0, 1);
        sum0 += __shfl_xor_sync(0xFFFFFFFFu, sum0, 2);
        sum1 += __shfl_xor_sync(0xFFFFFFFFu, sum1, 1);
        sum1 += __shfl_xor_sync(0xFFFFFFFFu, sum1, 2);
        lr0 = lr0 * corr0 + sum0;
        lr1 = lr1 * corr1 + sum1;
        mr0 = mn0; mr1 = mn1;
        #pragma unroll
        for (int q = 0; q < 16; q++) {
            o[q][0] *= corr0; o[q][1] *= corr0;
            o[q][2] *= corr1; o[q][3] *= corr1;
        }

        uint32_t ph[8][2], pl[8][2];
        #pragma unroll
        for (int a = 0; a < 8; a++) {
            float p0 = s[a][0], p1 = s[a][1], p2 = s[a][2], p3 = s[a][3];
            ph[a][0] = packbf(p0, p1);
            ph[a][1] = packbf(p2, p3);
            float r0 = p0 - __bfloat162float(__float2bfloat16(p0));
            float r1 = p1 - __bfloat162float(__float2bfloat16(p1));
            float r2 = p2 - __bfloat162float(__float2bfloat16(p2));
            float r3 = p3 - __bfloat162float(__float2bfloat16(p3));
            pl[a][0] = packbf(r0, r1);
            pl[a][1] = packbf(r2, r3);
        }

        #pragma unroll
        for (int kk = 0; kk < 4; kk++) {
            uint32_t ahh[4] = {ph[2*kk][0], ph[2*kk][1], ph[2*kk+1][0], ph[2*kk+1][1]};
            uint32_t ahl[4] = {pl[2*kk][0], pl[2*kk][1], pl[2*kk+1][0], pl[2*kk+1][1]};
            #pragma unroll
            for (int q = 0; q < 8; q++) {
                uint32_t vh[4], vl[4];
                LDSM4T(vh, vb_hi + v_off + kk * (16 * 272) + q * 32);
                LDSM4T(vl, vb_lo + v_off + kk * (16 * 272) + q * 32);
                mma_bf16(o[2*q],   ahh, vh[0], vh[1]);
                mma_bf16(o[2*q+1], ahh, vh[2], vh[3]);
                mma_bf16(o[2*q],   ahh, vl[0], vl[1]);
                mma_bf16(o[2*q+1], ahh, vl[2], vl[3]);
                mma_bf16(o[2*q],   ahl, vh[0], vh[1]);
                mma_bf16(o[2*q+1], ahl, vh[2], vh[3]);
            }
        }
        CP_WAIT0(); __syncthreads();
    }

    // epilogue: O /= l, split to bf16 hi/lo for the WO GEMM
    float i0 = 1.f / lr0, i1 = 1.f / lr1;
    int r0 = t0 + w * 16 + (lane >> 2);
    size_t base0 = ((size_t)(b * TSEQ + r0)) * CDIM + h * HDIM + (lane & 3) * 2;
    size_t base1 = base0 + (size_t)8 * CDIM;
    #pragma unroll
    for (int q = 0; q < 16; q++) {
        uint32_t hh, ll;
        split2(o[q][0] * i0, o[q][1] * i0, hh, ll);
        *(uint32_t*)(g_yhi + base0 + q * 8) = hh;
        *(uint32_t*)(g_ylo + base0 + q * 8) = ll;
        split2(o[q][2] * i1, o[q][3] * i1, hh, ll);
        *(uint32_t*)(g_yhi + base1 + q * 8) = hh;
        *(uint32_t*)(g_ylo + base1 + q * 8) = ll;
    }
}

// ---------------------------------------------------------------------------
extern "C" void kernel_launch(void* const* d_in, const int* in_sizes, int n_in,
                              void* d_out, int out_size)
{
    (void)in_sizes; (void)n_in; (void)out_size;
    const float* x    = (const float*)d_in[0];
    const float* cosp = (const float*)d_in[1];
    const float* sinp = (const float*)d_in[2];
    const float* wq   = (const float*)d_in[3];
    const float* wk   = (const float*)d_in[4];
    const float* wv   = (const float*)d_in[5];
    const float* wo   = (const float*)d_in[6];
    float* out = (float*)d_out;

    __nv_bfloat16 *xhi, *xlo, *whi, *wlo;
    cudaGetSymbolAddress((void**)&xhi, g_xhi);
    cudaGetSymbolAddress((void**)&xlo, g_xlo);
    cudaGetSymbolAddress((void**)&whi, g_whi);
    cudaGetSymbolAddress((void**)&wlo, g_wlo);

    const size_t W = (size_t)CDIM * CDIM;
    const int n4x = MROWS * CDIM / 4;
    const int n4w = CDIM * CDIM / 4;

    split_kernel<<<n4x / 256, 256>>>(x,  xhi,         xlo,         n4x);
    split_kernel<<<n4w / 256, 256>>>(wq, whi + 0 * W, wlo + 0 * W, n4w);
    split_kernel<<<n4w / 256, 256>>>(wk, whi + 1 * W, wlo + 1 * W, n4w);
    split_kernel<<<n4w / 256, 256>>>(wv, whi + 2 * W, wlo + 2 * W, n4w);
    split_kernel<<<n4w / 256, 256>>>(wo, whi + 3 * W, wlo + 3 * W, n4w);

    cudaFuncSetAttribute(gemm_fused,
                         cudaFuncAttributeMaxDynamicSharedMemorySize, GSMEM3);
    cudaFuncSetAttribute(flash_mma,
                         cudaFuncAttributeMaxDynamicSharedMemorySize, FSMEM);

    // fused QKV: z = 0(Q,rope) 1(K,rope) 2(V)
    gemm_fused<<<dim3(CDIM / 256, MROWS / 128, 3), 256, GSMEM3>>>(0, cosp, sinp, out);

    flash_mma<<<dim3(TSEQ / 128, NHEAD, BATCH), 256, FSMEM>>>();

    // output projection
    gemm_fused<<<dim3(CDIM / 256, MROWS / 128, 1), 256, GSMEM3>>>(1, cosp, sinp, out);
}